// round 1
// baseline (speedup 1.0000x reference)
#include <cuda_runtime.h>
#include <math.h>

#define NN   512        // nodes
#define KD   8          // edges per node
#define NNZ  4096       // incidences
#define FT   1386       // text features
#define HD   4096       // hidden
#define NH   8          // heads
#define NC   64         // code
#define EE   512        // hyperedges
#define HC   (NH*NC)    // 512
#define GC   (HC+NC)    // 576: [attention G | feat@W2]
#define WAC  (NH*HD)    // 32768, Wa row length

// ---------------- scratch (static device memory; no allocation) ----------------
__device__ float g_xl[NN*HD];        // x @ W1
__device__ float g_ef[EE*HD];        // edge_feat of hgc1
__device__ float g_he[EE*HD];        // hyperedge attr (per-edge mean of feat)
__device__ float g_Bcat[HD*GC];      // [k][h*64+c]=M, [k][512+c]=W2  (B of G-GEMM)
__device__ float g_V1[HD*NH];        // Wa contracted with att[:, :HID]   [k][h]
__device__ float g_V2[HD*NH];        // Wa contracted with att[:, HID:]   [k][h]
__device__ float g_sx[NN*NH];
__device__ float g_se[EE*NH];
__device__ float g_alpha[NNZ*NH];
__device__ float g_G[NN*GC];         // feat @ Bcat
__device__ float g_R[EE*HC];         // edge_m @ W2
__device__ float g_Y[NN*NC];         // hid_cat @ W2
__device__ float g_ef2[EE*NC];
__device__ float g_bw2[NC];          // ba @ W2
__device__ int   g_bcnt[EE];
__device__ int   g_dcnt[NN];
__device__ int   g_boff[EE];
__device__ int   g_csr[NNZ];
__device__ float g_Binv[EE];
__device__ float g_Dinv[NN];

// ---------------- degree / CSR (deterministic) ----------------
__global__ void k_zero() {
    int t = threadIdx.x;
    if (t < EE) g_bcnt[t] = 0;
    if (t < NN) g_dcnt[t] = 0;
}

__global__ void k_count(const int* __restrict__ node, const int* __restrict__ edge) {
    int i = blockIdx.x * blockDim.x + threadIdx.x;
    if (i < NNZ) {
        atomicAdd(&g_bcnt[edge[i]], 1);
        atomicAdd(&g_dcnt[node[i]], 1);
    }
}

__global__ void k_scan() {
    __shared__ int s[EE];
    int t = threadIdx.x;
    int v = g_bcnt[t];
    s[t] = v;
    __syncthreads();
    for (int o = 1; o < EE; o <<= 1) {
        int add = (t >= o) ? s[t - o] : 0;
        __syncthreads();
        s[t] += add;
        __syncthreads();
    }
    g_boff[t] = s[t] - v;
    g_Binv[t] = (v > 0) ? 1.0f / (float)v : 0.0f;
    int d = g_dcnt[t];
    g_Dinv[t] = (d > 0) ? 1.0f / (float)d : 0.0f;
}

__global__ void __launch_bounds__(256) k_csr(const int* __restrict__ edge) {
    __shared__ int se_[NNZ];  // 16 KB
    for (int i = threadIdx.x; i < NNZ; i += blockDim.x) se_[i] = edge[i];
    __syncthreads();
    int i = blockIdx.x * blockDim.x + threadIdx.x;
    if (i < NNZ) {
        int e = se_[i];
        int r = 0;
        for (int j = 0; j < i; j++) r += (se_[j] == e) ? 1 : 0;   // deterministic rank
        g_csr[g_boff[e] + r] = i;
    }
}

// ---------------- generic fp32 GEMM: 64x64 tile, BK=16, 256 thr, 4x4 micro ----------------
__device__ __forceinline__ void gemm_tile(const float* __restrict__ A, int lda,
                                          const float* __restrict__ B, int ldb,
                                          float* __restrict__ C, int ldc, int Kk) {
    __shared__ float As[16][68];   // padded, 16B-aligned rows for LDS.128
    __shared__ float Bs[16][64];
    int tid = threadIdx.x;
    int ty = tid >> 4, tx = tid & 15;
    int m0 = blockIdx.x * 64, n0 = blockIdx.y * 64;
    float acc[4][4] = {};
    int nt = (Kk + 15) >> 4;
    for (int kt = 0; kt < nt; kt++) {
        int k0 = kt << 4;
#pragma unroll
        for (int p = 0; p < 4; p++) {
            int l = tid + (p << 8);
            int r = l >> 4, kk = l & 15;
            int kg = k0 + kk;
            As[kk][r] = (kg < Kk) ? A[(m0 + r) * lda + kg] : 0.0f;
        }
#pragma unroll
        for (int p = 0; p < 4; p++) {
            int l = tid + (p << 8);
            int kk = l >> 6, c = l & 63;
            int kg = k0 + kk;
            Bs[kk][c] = (kg < Kk) ? B[kg * ldb + n0 + c] : 0.0f;
        }
        __syncthreads();
#pragma unroll
        for (int kk = 0; kk < 16; kk++) {
            float4 av = *reinterpret_cast<const float4*>(&As[kk][ty << 2]);
            float4 bv = *reinterpret_cast<const float4*>(&Bs[kk][tx << 2]);
            float a[4] = {av.x, av.y, av.z, av.w};
            float b[4] = {bv.x, bv.y, bv.z, bv.w};
#pragma unroll
            for (int i = 0; i < 4; i++)
#pragma unroll
                for (int j = 0; j < 4; j++) acc[i][j] += a[i] * b[j];
        }
        __syncthreads();
    }
#pragma unroll
    for (int i = 0; i < 4; i++)
#pragma unroll
        for (int j = 0; j < 4; j++)
            C[(m0 + (ty << 2) + i) * ldc + n0 + (tx << 2) + j] = acc[i][j];
}

__global__ void __launch_bounds__(256) k_gemm1(const float* __restrict__ x,
                                               const float* __restrict__ W1) {
    gemm_tile(x, FT, W1, HD, g_xl, HD, FT);      // [512,1386]@[1386,4096]
}

__global__ void __launch_bounds__(256) k_gemmG(const float* __restrict__ feat) {
    gemm_tile(feat, HD, g_Bcat, GC, g_G, GC, HD); // [512,4096]@[4096,576]
}

// ---------------- fused M = Wa_h @ W2 and V = Wa_h @ att_h over one Wa pass ----------------
__global__ void __launch_bounds__(256) k_gemmMV(const float* __restrict__ Wa,
                                                const float* __restrict__ W2,
                                                const float* __restrict__ att) {
    __shared__ float As[16][68];
    __shared__ float Bs[16][64];
    int tid = threadIdx.x;
    int ty = tid >> 4, tx = tid & 15;
    int k0 = blockIdx.x * 64;   // 64 Wa-rows (k) per block
    int h  = blockIdx.y;        // head
    const float* Ab  = Wa + (size_t)h * HD;          // Wa[k*WAC + h*HD + d]
    const float* at1 = att + (size_t)h * 2 * HD;     // att[h, :HID]
    const float* at2 = at1 + HD;                     // att[h, HID:]
    float acc[4][4] = {};
    float pv1 = 0.0f, pv2 = 0.0f;                    // per-thread V partials
    int ar  = tid >> 2;          // A load: row 0..63
    int akk = (tid & 3) << 2;    // A load: kk quad
    int bkk = tid >> 4;          // B load: kk 0..15
    int bc  = (tid & 15) << 2;   // B load: col quad
    for (int kt = 0; kt < HD / 16; kt++) {
        int d0 = kt << 4;
        float4 va = *reinterpret_cast<const float4*>(&Ab[(size_t)(k0 + ar) * WAC + d0 + akk]);
        As[akk + 0][ar] = va.x; As[akk + 1][ar] = va.y;
        As[akk + 2][ar] = va.z; As[akk + 3][ar] = va.w;
        // V accumulation amortized into the A-load (att rows are L1-resident)
        pv1 += va.x * __ldg(&at1[d0 + akk]) + va.y * __ldg(&at1[d0 + akk + 1])
             + va.z * __ldg(&at1[d0 + akk + 2]) + va.w * __ldg(&at1[d0 + akk + 3]);
        pv2 += va.x * __ldg(&at2[d0 + akk]) + va.y * __ldg(&at2[d0 + akk + 1])
             + va.z * __ldg(&at2[d0 + akk + 2]) + va.w * __ldg(&at2[d0 + akk + 3]);
        float4 vb = *reinterpret_cast<const float4*>(&W2[(d0 + bkk) * NC + bc]);
        *reinterpret_cast<float4*>(&Bs[bkk][bc]) = vb;
        __syncthreads();
#pragma unroll
        for (int kk = 0; kk < 16; kk++) {
            float4 av = *reinterpret_cast<const float4*>(&As[kk][ty << 2]);
            float4 bv = *reinterpret_cast<const float4*>(&Bs[kk][tx << 2]);
            float a[4] = {av.x, av.y, av.z, av.w};
            float b[4] = {bv.x, bv.y, bv.z, bv.w};
#pragma unroll
            for (int i = 0; i < 4; i++)
#pragma unroll
                for (int j = 0; j < 4; j++) acc[i][j] += a[i] * b[j];
        }
        __syncthreads();
    }
    // write M into Bcat (B matrix of the later G-GEMM): row=k, col=h*64+c
#pragma unroll
    for (int i = 0; i < 4; i++) {
        int k = k0 + (ty << 2) + i;
#pragma unroll
        for (int j = 0; j < 4; j++)
            g_Bcat[k * GC + h * NC + (tx << 2) + j] = acc[i][j];
    }
    // reduce V partials: 4 threads (same ar, different akk) per k-row
    __shared__ float vr1[256], vr2[256];
    vr1[tid] = pv1; vr2[tid] = pv2;
    __syncthreads();
    if ((tid & 3) == 0) {
        int k = k0 + ar;
        g_V1[k * NH + h] = vr1[tid] + vr1[tid + 1] + vr1[tid + 2] + vr1[tid + 3];
        g_V2[k * NH + h] = vr2[tid] + vr2[tid + 1] + vr2[tid + 2] + vr2[tid + 3];
    }
}

__global__ void k_copyW2(const float* __restrict__ W2) {
    int i = blockIdx.x * blockDim.x + threadIdx.x;   // HD*NC
    if (i < HD * NC) {
        int d = i >> 6, c = i & 63;
        g_Bcat[d * GC + HC + c] = W2[i];
    }
}

// ---------------- hgc1: edge gather, node gather + relu, hyperedge mean ----------------
__global__ void __launch_bounds__(256) k_edgefeat() {
    int e = blockIdx.x;
    int d = blockIdx.y * 256 + threadIdx.x;
    int off = g_boff[e], cnt = g_bcnt[e];
    float acc = 0.0f;
    for (int t = 0; t < cnt; t++) {
        int i = g_csr[off + t];
        acc += g_xl[(size_t)(i >> 3) * HD + d];
    }
    g_ef[(size_t)e * HD + d] = acc * g_Binv[e];
}

__global__ void __launch_bounds__(256) k_feat(const int* __restrict__ edge,
                                              const float* __restrict__ b1,
                                              float* __restrict__ feat) {
    int n = blockIdx.x;
    int d = blockIdx.y * 256 + threadIdx.x;
    float acc = 0.0f;
#pragma unroll
    for (int j = 0; j < KD; j++) {
        int e = edge[n * KD + j];
        acc += g_ef[(size_t)e * HD + d];
    }
    float v = acc * g_Dinv[n] + b1[d];
    feat[(size_t)n * HD + d] = v > 0.0f ? v : 0.0f;   // relu
}

__global__ void __launch_bounds__(256) k_he(const float* __restrict__ feat) {
    int e = blockIdx.x;
    int d = blockIdx.y * 256 + threadIdx.x;
    int off = g_boff[e], cnt = g_bcnt[e];
    float acc = 0.0f;
    for (int t = 0; t < cnt; t++) {
        int i = g_csr[off + t];
        acc += feat[(size_t)(i >> 3) * HD + d];
    }
    g_he[(size_t)e * HD + d] = acc / (float)cnt;
}

// ---------------- attention logits: sx / se (row dot V) ----------------
__global__ void __launch_bounds__(256) k_sxse(const float* __restrict__ feat) {
    int b = blockIdx.x;
    const float* row; const float* V; float* out;
    if (b < NN) { row = feat + (size_t)b * HD; V = g_V1; out = g_sx + b * NH; }
    else { int e = b - NN; row = g_he + (size_t)e * HD; V = g_V2; out = g_se + e * NH; }
    float acc[NH] = {};
    for (int k = threadIdx.x; k < HD; k += 256) {
        float xv = row[k];
        float4 w0 = *reinterpret_cast<const float4*>(&V[k * NH]);
        float4 w1 = *reinterpret_cast<const float4*>(&V[k * NH + 4]);
        acc[0] += xv * w0.x; acc[1] += xv * w0.y; acc[2] += xv * w0.z; acc[3] += xv * w0.w;
        acc[4] += xv * w1.x; acc[5] += xv * w1.y; acc[6] += xv * w1.z; acc[7] += xv * w1.w;
    }
    __shared__ float red[NH][256];
#pragma unroll
    for (int h = 0; h < NH; h++) red[h][threadIdx.x] = acc[h];
    __syncthreads();
    for (int s = 128; s > 0; s >>= 1) {
        if (threadIdx.x < s) {
#pragma unroll
            for (int h = 0; h < NH; h++) red[h][threadIdx.x] += red[h][threadIdx.x + s];
        }
        __syncthreads();
    }
    if (threadIdx.x < NH) out[threadIdx.x] = red[threadIdx.x][0];
}

// ---------------- per-node segment softmax (leaky_relu logits) ----------------
__global__ void k_alpha(const int* __restrict__ edge) {
    int id = blockIdx.x * blockDim.x + threadIdx.x;
    if (id >= NN * NH) return;
    int n = id >> 3, h = id & 7;
    float sxv = g_sx[n * NH + h];
    float l[KD];
    float m = -1e30f;
#pragma unroll
    for (int j = 0; j < KD; j++) {
        int e = edge[n * KD + j];
        float t = sxv + g_se[e * NH + h];
        t = t > 0.0f ? t : 0.2f * t;          // leaky_relu(0.2)
        l[j] = t;
        m = fmaxf(m, t);
    }
    float s = 0.0f;
#pragma unroll
    for (int j = 0; j < KD; j++) { l[j] = expf(l[j] - m); s += l[j]; }
    float inv = 1.0f / s;
#pragma unroll
    for (int j = 0; j < KD; j++) g_alpha[(n * KD + j) * NH + h] = l[j] * inv;
}

// ---------------- attention aggregation in CODE space ----------------
__global__ void __launch_bounds__(256) k_R() {       // R = edge_m @ W2
    int e = blockIdx.x;
    int hc = blockIdx.y * 256 + threadIdx.x;         // 0..511
    int h = hc >> 6;
    int off = g_boff[e], cnt = g_bcnt[e];
    float acc = 0.0f;
    for (int t = 0; t < cnt; t++) {
        int i = g_csr[off + t];
        acc += g_alpha[i * NH + h] * g_G[(i >> 3) * GC + hc];
    }
    g_R[e * HC + hc] = acc * g_Binv[e];
}

__global__ void k_bw2(const float* __restrict__ ba, const float* __restrict__ W2) {
    int tid = threadIdx.x;
    int c = tid & 63, sl = tid >> 6;                 // 4 K-slices per column
    float acc = 0.0f;
    for (int d = sl * 1024; d < (sl + 1) * 1024; d++) acc += ba[d] * W2[d * NC + c];
    __shared__ float r[256];
    r[tid] = acc;
    __syncthreads();
    if (sl == 0) g_bw2[c] = r[c] + r[c + 64] + r[c + 128] + r[c + 192];
}

__global__ void k_Y(const int* __restrict__ edge) {  // Y = hid_cat @ W2
    int n = blockIdx.x, c = threadIdx.x;
    float acc = g_G[n * GC + HC + c] + g_bw2[c];     // feat@W2 + ba@W2
    float s = 0.0f;
#pragma unroll
    for (int j = 0; j < KD; j++) {
        int e = edge[n * KD + j];
        const float* al = &g_alpha[(n * KD + j) * NH];
        const float* Rr = &g_R[e * HC + c];
#pragma unroll
        for (int h = 0; h < NH; h++) s += al[h] * Rr[h * NC];
    }
    g_Y[n * NC + c] = acc + s * g_Dinv[n] * (1.0f / NH);  // mean over heads * Dinv
}

// ---------------- final plain hg-conv in CODE space + tanh ----------------
__global__ void k_ef2() {
    int e = blockIdx.x, c = threadIdx.x;
    int off = g_boff[e], cnt = g_bcnt[e];
    float acc = 0.0f;
    for (int t = 0; t < cnt; t++) {
        int i = g_csr[off + t];
        acc += g_Y[(i >> 3) * NC + c];
    }
    g_ef2[e * NC + c] = acc * g_Binv[e];
}

__global__ void k_out(const int* __restrict__ edge, const float* __restrict__ b2,
                      float* __restrict__ out) {
    int n = blockIdx.x, c = threadIdx.x;
    float acc = 0.0f;
#pragma unroll
    for (int j = 0; j < KD; j++) {
        int e = edge[n * KD + j];
        acc += g_ef2[e * NC + c];
    }
    float hid = acc * g_Dinv[n] + b2[c];
    out[(size_t)NN * HD + n * NC + c] = hid;                      // hid
    out[(size_t)NN * HD + NN * NC + n * NC + c] = tanhf(hid);     // code
}

// ---------------- launch ----------------
extern "C" void kernel_launch(void* const* d_in, const int* in_sizes, int n_in,
                              void* d_out, int out_size) {
    const float* x    = (const float*)d_in[0];
    const int*   node = (const int*)  d_in[1];
    const int*   edge = (const int*)  d_in[2];
    const float* W1   = (const float*)d_in[3];
    const float* b1   = (const float*)d_in[4];
    const float* Wa   = (const float*)d_in[5];
    const float* att  = (const float*)d_in[6];
    const float* ba   = (const float*)d_in[7];
    const float* W2   = (const float*)d_in[8];
    const float* b2   = (const float*)d_in[9];
    float* out  = (float*)d_out;
    float* feat = out;   // feat lives directly in the output buffer

    k_zero<<<1, 512>>>();
    k_count<<<16, 256>>>(node, edge);
    k_scan<<<1, 512>>>();
    k_csr<<<16, 256>>>(edge);

    k_gemm1<<<dim3(8, 64), 256>>>(x, W1);            // xl = x @ W1
    k_edgefeat<<<dim3(EE, 16), 256>>>();
    k_feat<<<dim3(NN, 16), 256>>>(edge, b1, feat);   // feat (output #1)
    k_he<<<dim3(EE, 16), 256>>>(feat);

    k_gemmMV<<<dim3(64, 8), 256>>>(Wa, W2, att);     // M (->Bcat) + V1/V2, one Wa pass
    k_copyW2<<<1024, 256>>>(W2);                     // Bcat cols 512..575 = W2

    k_sxse<<<NN + EE, 256>>>(feat);
    k_alpha<<<16, 256>>>(edge);

    k_gemmG<<<dim3(8, 9), 256>>>(feat);              // G = feat @ [M | W2]
    k_R<<<dim3(EE, 2), 256>>>();
    k_bw2<<<1, 256>>>(ba, W2);
    k_Y<<<NN, 64>>>(edge);

    k_ef2<<<EE, 64>>>();
    k_out<<<NN, 64>>>(edge, b2, out);                // hid (#2) + code (#3)
}

// round 3
// speedup vs baseline: 2.0760x; 2.0760x over previous
#include <cuda_runtime.h>
#include <math.h>
#include <stdint.h>

#define NN   512        // nodes
#define KD   8          // edges per node
#define NNZ  4096       // incidences
#define FT   1386       // text features
#define FTP  1408       // padded to 32-multiple
#define HD   4096       // hidden
#define NH   8          // heads
#define NC   64         // code
#define EE   512        // hyperedges
#define HC   (NH*NC)    // 512
#define GC   (HC+NC)    // 576
#define WAC  (NH*HD)    // 32768
#define BR   80         // B rows for MV gemm: 64 W2T + att1 + att2 + 14 pad

// ---------------- scratch (static device memory) ----------------
__device__ float g_xpad[NN*FTP];      // tf32-rounded x, padded
__device__ float g_W1T[HD*FTP];       // tf32-rounded W1^T
__device__ float g_W2T[NC*HD];        // tf32-rounded W2^T
__device__ float g_Ball[NH*BR*HD];    // per-head B for MV gemm (rounded)
__device__ float g_BcatT[GC*HD];      // rows 0..511 = M^T (rounded); 512..575 = W2T
__device__ float g_xl[NN*HD];
__device__ float g_ef[EE*HD];
__device__ float g_he[EE*HD];
__device__ float g_featc[NN*HD];      // tf32-rounded feat (A of G gemm)
__device__ float g_V1[HD*NH];
__device__ float g_V2[HD*NH];
__device__ float g_sx[NN*NH];
__device__ float g_se[EE*NH];
__device__ float g_alpha[NNZ*NH];
__device__ float g_G[NN*GC];
__device__ float g_R[EE*HC];
__device__ float g_Y[NN*NC];
__device__ float g_ef2[EE*NC];
__device__ float g_bw2[NC];
__device__ int   g_bcnt[EE];
__device__ int   g_dcnt[NN];
__device__ int   g_boff[EE];
__device__ int   g_csr[NNZ];
__device__ float g_Binv[EE];
__device__ float g_Dinv[NN];

// ---------------- tf32 helpers (arch-portable, sm_80+) ----------------
__device__ __forceinline__ float tf32r(float x) {
    float y;
    asm("cvt.rna.tf32.f32 %0, %1;" : "=f"(y) : "f"(x));
    return y;
}

#define MMA_TF32(C, A0, A1, A2, A3, B0, B1) \
    asm volatile("mma.sync.aligned.m16n8k8.row.col.f32.tf32.tf32.f32 " \
        "{%0,%1,%2,%3},{%4,%5,%6,%7},{%8,%9},{%0,%1,%2,%3};" \
        : "+f"((C)[0]), "+f"((C)[1]), "+f"((C)[2]), "+f"((C)[3]) \
        : "r"(A0), "r"(A1), "r"(A2), "r"(A3), "r"(B0), "r"(B1))

// ============ tf32 mma.sync mainloop: acc += A[128 x 32*NCH] * B[BN x 32*NCH]^T ============
// 256 threads, 8 warps in 4(M) x 2(N). Warp tile: 32 x (BN/2).
template<int BN, int NCH, bool CVTA>
__device__ __forceinline__ void mma_mainloop(const float* __restrict__ A, size_t lda,
                                             const float* __restrict__ B, size_t ldb,
                                             float (&acc)[2][BN/16][4]) {
    constexpr int NT = BN / 16;
    constexpr int PBN = (BN * 16) / 256;      // float2 B loads per thread
    __shared__ float As[128][36];
    __shared__ float Bs[BN][36];
    const int tid = threadIdx.x, lane = tid & 31, wid = tid >> 5;
    const int wm = wid >> 1, wn = wid & 1;
    const int ar = tid >> 3, ac = (tid & 7) * 4;
    const int fr = lane >> 2, fq = lane & 3;
    float4 pa[4];
    float2 pb[PBN];

    // prologue load (chunk 0)
#pragma unroll
    for (int p = 0; p < 4; p++)
        pa[p] = *(const float4*)&A[(size_t)(ar + p * 32) * lda + ac];
#pragma unroll
    for (int p = 0; p < PBN; p++) {
        int idx = tid + p * 256;
        pb[p] = *(const float2*)&B[(size_t)(idx >> 4) * ldb + (idx & 15) * 2];
    }

    for (int c = 0; c < NCH; c++) {
        __syncthreads();
#pragma unroll
        for (int p = 0; p < 4; p++) {
            float4 v = pa[p];
            if (CVTA) { v.x = tf32r(v.x); v.y = tf32r(v.y);
                        v.z = tf32r(v.z); v.w = tf32r(v.w); }
            *(float4*)&As[ar + p * 32][ac] = v;
        }
#pragma unroll
        for (int p = 0; p < PBN; p++) {
            int idx = tid + p * 256;
            *(float2*)&Bs[idx >> 4][(idx & 15) * 2] = pb[p];
        }
        __syncthreads();
        if (c + 1 < NCH) {
            int d0 = (c + 1) * 32;
#pragma unroll
            for (int p = 0; p < 4; p++)
                pa[p] = *(const float4*)&A[(size_t)(ar + p * 32) * lda + d0 + ac];
#pragma unroll
            for (int p = 0; p < PBN; p++) {
                int idx = tid + p * 256;
                pb[p] = *(const float2*)&B[(size_t)(idx >> 4) * ldb + d0 + (idx & 15) * 2];
            }
        }
#pragma unroll
        for (int kk = 0; kk < 4; kk++) {
            int kc = kk * 8 + fq;
            uint32_t afr[2][4];
#pragma unroll
            for (int mt = 0; mt < 2; mt++) {
                int r0 = wm * 32 + mt * 16 + fr;
                afr[mt][0] = __float_as_uint(As[r0][kc]);
                afr[mt][1] = __float_as_uint(As[r0 + 8][kc]);
                afr[mt][2] = __float_as_uint(As[r0][kc + 4]);
                afr[mt][3] = __float_as_uint(As[r0 + 8][kc + 4]);
            }
#pragma unroll
            for (int nt = 0; nt < NT; nt++) {
                int nr = wn * (BN / 2) + nt * 8 + fr;
                uint32_t b0 = __float_as_uint(Bs[nr][kc]);
                uint32_t b1 = __float_as_uint(Bs[nr][kc + 4]);
#pragma unroll
                for (int mt = 0; mt < 2; mt++)
                    MMA_TF32(acc[mt][nt], afr[mt][0], afr[mt][1], afr[mt][2], afr[mt][3], b0, b1);
            }
        }
    }
}

// ---------------- GEMM kernels ----------------
__global__ void __launch_bounds__(256) k_tg1() {       // xl = xpad @ W1T^T
    float acc[2][4][4] = {};
    const float* A = g_xpad + (size_t)blockIdx.x * 128 * FTP;
    const float* B = g_W1T + (size_t)blockIdx.y * 64 * FTP;
    mma_mainloop<64, FTP / 32, false>(A, FTP, B, FTP, acc);
    int lane = threadIdx.x & 31, wid = threadIdx.x >> 5;
    int rb = blockIdx.x * 128 + (wid >> 1) * 32 + (lane >> 2);
    int cb = blockIdx.y * 64 + (wid & 1) * 32 + 2 * (lane & 3);
#pragma unroll
    for (int mt = 0; mt < 2; mt++)
#pragma unroll
        for (int nt = 0; nt < 4; nt++) {
            int r = rb + mt * 16, cc = cb + nt * 8;
            *(float2*)&g_xl[(size_t)r * HD + cc] = make_float2(acc[mt][nt][0], acc[mt][nt][1]);
            *(float2*)&g_xl[(size_t)(r + 8) * HD + cc] = make_float2(acc[mt][nt][2], acc[mt][nt][3]);
        }
}

__global__ void __launch_bounds__(256) k_tgG() {       // G = featc @ BcatT^T
    float acc[2][4][4] = {};
    const float* A = g_featc + (size_t)blockIdx.x * 128 * HD;
    const float* B = g_BcatT + (size_t)blockIdx.y * 64 * HD;
    mma_mainloop<64, HD / 32, false>(A, HD, B, HD, acc);
    int lane = threadIdx.x & 31, wid = threadIdx.x >> 5;
    int rb = blockIdx.x * 128 + (wid >> 1) * 32 + (lane >> 2);
    int cb = blockIdx.y * 64 + (wid & 1) * 32 + 2 * (lane & 3);
#pragma unroll
    for (int mt = 0; mt < 2; mt++)
#pragma unroll
        for (int nt = 0; nt < 4; nt++) {
            int r = rb + mt * 16, cc = cb + nt * 8;
            *(float2*)&g_G[(size_t)r * GC + cc] = make_float2(acc[mt][nt][0], acc[mt][nt][1]);
            *(float2*)&g_G[(size_t)(r + 8) * GC + cc] = make_float2(acc[mt][nt][2], acc[mt][nt][3]);
        }
}

__global__ void __launch_bounds__(256) k_tgMV(const float* __restrict__ Wa) {
    float acc[2][5][4] = {};
    int h = blockIdx.y;
    const float* A = Wa + (size_t)h * HD + (size_t)blockIdx.x * 128 * WAC;
    const float* B = g_Ball + (size_t)h * BR * HD;
    mma_mainloop<80, HD / 32, true>(A, WAC, B, HD, acc);
    int lane = threadIdx.x & 31, wid = threadIdx.x >> 5;
    int k0 = blockIdx.x * 128 + (wid >> 1) * 32 + (lane >> 2);
    int nb = (wid & 1) * 40 + 2 * (lane & 3);
#pragma unroll
    for (int mt = 0; mt < 2; mt++) {
        int k = k0 + mt * 16;
#pragma unroll
        for (int nt = 0; nt < 5; nt++) {
            int n = nb + nt * 8;
            if (n < 64) {
                g_BcatT[(size_t)(h * 64 + n) * HD + k]         = tf32r(acc[mt][nt][0]);
                g_BcatT[(size_t)(h * 64 + n + 1) * HD + k]     = tf32r(acc[mt][nt][1]);
                g_BcatT[(size_t)(h * 64 + n) * HD + k + 8]     = tf32r(acc[mt][nt][2]);
                g_BcatT[(size_t)(h * 64 + n + 1) * HD + k + 8] = tf32r(acc[mt][nt][3]);
            } else if (n == 64) {
                g_V1[k * NH + h]       = acc[mt][nt][0];
                g_V2[k * NH + h]       = acc[mt][nt][1];
                g_V1[(k + 8) * NH + h] = acc[mt][nt][2];
                g_V2[(k + 8) * NH + h] = acc[mt][nt][3];
            }
        }
    }
}

// ---------------- prep kernels (apply tf32 rounding) ----------------
__global__ void k_xpad(const float* __restrict__ x) {
    int i = blockIdx.x * 256 + threadIdx.x;
    if (i < NN * FTP) {
        int r = i / FTP, c = i % FTP;
        g_xpad[i] = (c < FT) ? tf32r(x[r * FT + c]) : 0.0f;
    }
}
__global__ void k_W1T(const float* __restrict__ W1) {   // [FT,HD] -> [HD,FTP], rounded
    __shared__ float t[32][33];
    int kb = blockIdx.y * 32, nb = blockIdx.x * 32;
    int tx = threadIdx.x, ty = threadIdx.y;
    for (int i = ty; i < 32; i += 8) {
        int k = kb + i;
        t[i][tx] = (k < FT) ? tf32r(W1[(size_t)k * HD + nb + tx]) : 0.0f;
    }
    __syncthreads();
    for (int i = ty; i < 32; i += 8)
        g_W1T[(size_t)(nb + i) * FTP + kb + tx] = t[tx][i];
}
__global__ void k_W2T(const float* __restrict__ W2) {   // [HD,NC] -> [NC,HD], rounded
    __shared__ float t[32][33];
    int kb = blockIdx.y * 32, nb = blockIdx.x * 32;
    int tx = threadIdx.x, ty = threadIdx.y;
    for (int i = ty; i < 32; i += 8)
        t[i][tx] = tf32r(W2[(size_t)(kb + i) * NC + nb + tx]);
    __syncthreads();
    for (int i = ty; i < 32; i += 8)
        g_W2T[(size_t)(nb + i) * HD + kb + tx] = t[tx][i];
}
__global__ void k_fillB(const float* __restrict__ att) {
    size_t i = (size_t)blockIdx.x * 256 + threadIdx.x;    // NH*BR*HD
    if (i >= (size_t)NH * BR * HD) return;
    int d = (int)(i & (HD - 1));
    int rh = (int)(i >> 12);
    int r = rh % BR, h = rh / BR;
    float v;
    if (r < 64)       v = g_W2T[(size_t)r * HD + d];
    else if (r == 64) v = tf32r(att[h * 2 * HD + d]);
    else if (r == 65) v = tf32r(att[h * 2 * HD + HD + d]);
    else              v = 0.0f;
    g_Ball[i] = v;
}
__global__ void k_tailB() {                              // BcatT rows 512..575 = W2T
    int i = blockIdx.x * 256 + threadIdx.x;              // NC*HD
    g_BcatT[(size_t)HC * HD + i] = g_W2T[i];
}

// ---------------- degree / CSR ----------------
__global__ void k_zero() {
    int t = threadIdx.x;
    if (t < EE) g_bcnt[t] = 0;
    if (t < NN) g_dcnt[t] = 0;
}
__global__ void k_count(const int* __restrict__ node, const int* __restrict__ edge) {
    int i = blockIdx.x * blockDim.x + threadIdx.x;
    if (i < NNZ) {
        atomicAdd(&g_bcnt[edge[i]], 1);
        atomicAdd(&g_dcnt[node[i]], 1);
    }
}
__global__ void k_scan() {
    __shared__ int s[EE];
    int t = threadIdx.x;
    int v = g_bcnt[t];
    s[t] = v;
    __syncthreads();
    for (int o = 1; o < EE; o <<= 1) {
        int add = (t >= o) ? s[t - o] : 0;
        __syncthreads();
        s[t] += add;
        __syncthreads();
    }
    g_boff[t] = s[t] - v;
    g_Binv[t] = (v > 0) ? 1.0f / (float)v : 0.0f;
    int d = g_dcnt[t];
    g_Dinv[t] = (d > 0) ? 1.0f / (float)d : 0.0f;
}
__global__ void __launch_bounds__(512) k_csr2(const int* __restrict__ edge) {
    __shared__ int se_[NNZ];
    for (int i = threadIdx.x; i < NNZ; i += 512) se_[i] = edge[i];
    __syncthreads();
    int e = threadIdx.x;
    int w = g_boff[e];
    for (int i = 0; i < NNZ; i++)
        if (se_[i] == e) g_csr[w++] = i;
}

// ---------------- hgc1 gathers ----------------
__global__ void __launch_bounds__(256) k_edgefeat() {
    int e = blockIdx.x;
    int d = blockIdx.y * 256 + threadIdx.x;
    int off = g_boff[e], cnt = g_bcnt[e];
    float acc = 0.0f;
    for (int t = 0; t < cnt; t++) {
        int i = g_csr[off + t];
        acc += g_xl[(size_t)(i >> 3) * HD + d];
    }
    g_ef[(size_t)e * HD + d] = acc * g_Binv[e];
}
__global__ void __launch_bounds__(256) k_feat(const int* __restrict__ edge,
                                              const float* __restrict__ b1,
                                              float* __restrict__ feat) {
    int n = blockIdx.x;
    int d = blockIdx.y * 256 + threadIdx.x;
    float acc = 0.0f;
#pragma unroll
    for (int j = 0; j < KD; j++) {
        int e = edge[n * KD + j];
        acc += g_ef[(size_t)e * HD + d];
    }
    float v = acc * g_Dinv[n] + b1[d];
    v = v > 0.0f ? v : 0.0f;
    feat[(size_t)n * HD + d] = v;            // exact output #1
    g_featc[(size_t)n * HD + d] = tf32r(v);  // rounded A-operand for G gemm
}
__global__ void __launch_bounds__(256) k_he(const float* __restrict__ feat) {
    int e = blockIdx.x;
    int d = blockIdx.y * 256 + threadIdx.x;
    int off = g_boff[e], cnt = g_bcnt[e];
    float acc = 0.0f;
    for (int t = 0; t < cnt; t++) {
        int i = g_csr[off + t];
        acc += feat[(size_t)(i >> 3) * HD + d];
    }
    g_he[(size_t)e * HD + d] = acc / (float)cnt;
}

// ---------------- attention logits + softmax ----------------
__global__ void __launch_bounds__(256) k_sxse(const float* __restrict__ feat) {
    int b = blockIdx.x;
    const float* row; const float* V; float* out;
    if (b < NN) { row = feat + (size_t)b * HD; V = g_V1; out = g_sx + b * NH; }
    else { int e = b - NN; row = g_he + (size_t)e * HD; V = g_V2; out = g_se + e * NH; }
    float acc[NH] = {};
    for (int k = threadIdx.x; k < HD; k += 256) {
        float xv = row[k];
        float4 w0 = *(const float4*)&V[k * NH];
        float4 w1 = *(const float4*)&V[k * NH + 4];
        acc[0] += xv * w0.x; acc[1] += xv * w0.y; acc[2] += xv * w0.z; acc[3] += xv * w0.w;
        acc[4] += xv * w1.x; acc[5] += xv * w1.y; acc[6] += xv * w1.z; acc[7] += xv * w1.w;
    }
    __shared__ float red[NH][256];
#pragma unroll
    for (int h = 0; h < NH; h++) red[h][threadIdx.x] = acc[h];
    __syncthreads();
    for (int s = 128; s > 0; s >>= 1) {
        if (threadIdx.x < s) {
#pragma unroll
            for (int h = 0; h < NH; h++) red[h][threadIdx.x] += red[h][threadIdx.x + s];
        }
        __syncthreads();
    }
    if (threadIdx.x < NH) out[threadIdx.x] = red[threadIdx.x][0];
}
__global__ void k_alpha(const int* __restrict__ edge) {
    int id = blockIdx.x * blockDim.x + threadIdx.x;
    if (id >= NN * NH) return;
    int n = id >> 3, h = id & 7;
    float sxv = g_sx[n * NH + h];
    float l[KD];
    float m = -1e30f;
#pragma unroll
    for (int j = 0; j < KD; j++) {
        int e = edge[n * KD + j];
        float t = sxv + g_se[e * NH + h];
        t = t > 0.0f ? t : 0.2f * t;
        l[j] = t;
        m = fmaxf(m, t);
    }
    float s = 0.0f;
#pragma unroll
    for (int j = 0; j < KD; j++) { l[j] = expf(l[j] - m); s += l[j]; }
    float inv = 1.0f / s;
#pragma unroll
    for (int j = 0; j < KD; j++) g_alpha[(n * KD + j) * NH + h] = l[j] * inv;
}

// ---------------- CODE-space aggregation ----------------
__global__ void __launch_bounds__(256) k_R() {
    int e = blockIdx.x;
    int hc = blockIdx.y * 256 + threadIdx.x;
    int h = hc >> 6;
    int off = g_boff[e], cnt = g_bcnt[e];
    float acc = 0.0f;
    for (int t = 0; t < cnt; t++) {
        int i = g_csr[off + t];
        acc += g_alpha[i * NH + h] * g_G[(i >> 3) * GC + hc];
    }
    g_R[e * HC + hc] = acc * g_Binv[e];
}
__global__ void k_bw2(const float* __restrict__ ba, const float* __restrict__ W2) {
    int tid = threadIdx.x;
    int c = tid & 63, sl = tid >> 6;
    float acc = 0.0f;
    for (int d = sl * 1024; d < (sl + 1) * 1024; d++) acc += ba[d] * W2[d * NC + c];
    __shared__ float r[256];
    r[tid] = acc;
    __syncthreads();
    if (sl == 0) g_bw2[c] = r[c] + r[c + 64] + r[c + 128] + r[c + 192];
}
__global__ void k_Y(const int* __restrict__ edge) {
    int n = blockIdx.x, c = threadIdx.x;
    float acc = g_G[n * GC + HC + c] + g_bw2[c];
    float s = 0.0f;
#pragma unroll
    for (int j = 0; j < KD; j++) {
        int e = edge[n * KD + j];
        const float* al = &g_alpha[(n * KD + j) * NH];
        const float* Rr = &g_R[e * HC + c];
#pragma unroll
        for (int h = 0; h < NH; h++) s += al[h] * Rr[h * NC];
    }
    g_Y[n * NC + c] = acc + s * g_Dinv[n] * (1.0f / NH);
}
__global__ void k_ef2() {
    int e = blockIdx.x, c = threadIdx.x;
    int off = g_boff[e], cnt = g_bcnt[e];
    float acc = 0.0f;
    for (int t = 0; t < cnt; t++) {
        int i = g_csr[off + t];
        acc += g_Y[(i >> 3) * NC + c];
    }
    g_ef2[e * NC + c] = acc * g_Binv[e];
}
__global__ void k_out(const int* __restrict__ edge, const float* __restrict__ b2,
                      float* __restrict__ out) {
    int n = blockIdx.x, c = threadIdx.x;
    float acc = 0.0f;
#pragma unroll
    for (int j = 0; j < KD; j++) {
        int e = edge[n * KD + j];
        acc += g_ef2[e * NC + c];
    }
    float hid = acc * g_Dinv[n] + b2[c];
    out[(size_t)NN * HD + n * NC + c] = hid;
    out[(size_t)NN * HD + NN * NC + n * NC + c] = tanhf(hid);
}

// ---------------- launch ----------------
extern "C" void kernel_launch(void* const* d_in, const int* in_sizes, int n_in,
                              void* d_out, int out_size) {
    const float* x    = (const float*)d_in[0];
    const int*   node = (const int*)  d_in[1];
    const int*   edge = (const int*)  d_in[2];
    const float* W1   = (const float*)d_in[3];
    const float* b1   = (const float*)d_in[4];
    const float* Wa   = (const float*)d_in[5];
    const float* att  = (const float*)d_in[6];
    const float* ba   = (const float*)d_in[7];
    const float* W2   = (const float*)d_in[8];
    const float* b2   = (const float*)d_in[9];
    float* out  = (float*)d_out;
    float* feat = out;

    k_zero<<<1, 512>>>();
    k_count<<<16, 256>>>(node, edge);
    k_scan<<<1, 512>>>();
    k_csr2<<<1, 512>>>(edge);

    k_xpad<<<(NN * FTP + 255) / 256, 256>>>(x);
    k_W1T<<<dim3(HD / 32, FTP / 32), dim3(32, 8)>>>(W1);
    k_W2T<<<dim3(NC / 32, HD / 32), dim3(32, 8)>>>(W2);
    k_fillB<<<(NH * BR * HD + 255) / 256, 256>>>(att);
    k_tailB<<<(NC * HD) / 256, 256>>>();

    k_tg1<<<dim3(4, 64), 256>>>();                       // xl = x @ W1 (tf32)
    k_edgefeat<<<dim3(EE, 16), 256>>>();
    k_feat<<<dim3(NN, 16), 256>>>(edge, b1, feat);
    k_he<<<dim3(EE, 16), 256>>>(feat);

    k_tgMV<<<dim3(32, 8), 256>>>(Wa);                    // M^T -> BcatT, V1/V2 (tf32)

    k_sxse<<<NN + EE, 256>>>(feat);
    k_alpha<<<16, 256>>>(edge);

    k_tgG<<<dim3(4, 9), 256>>>();                        // G = feat @ [M | W2] (tf32)
    k_R<<<dim3(EE, 2), 256>>>();
    k_bw2<<<1, 256>>>(ba, W2);
    k_Y<<<NN, 64>>>(edge);

    k_ef2<<<EE, 64>>>();
    k_out<<<NN, 64>>>(edge, b2, out);
}

// round 4
// speedup vs baseline: 2.3892x; 1.1509x over previous
#include <cuda_runtime.h>
#include <math.h>
#include <stdint.h>

#define NN   512        // nodes
#define KD   8          // edges per node
#define NNZ  4096       // incidences
#define FT   1386       // text features
#define FTP  1408       // padded to 32-multiple
#define HD   4096       // hidden
#define NH   8          // heads
#define NC   64         // code
#define EE   512        // hyperedges
#define HC   (NH*NC)    // 512
#define GC   (HC+NC)    // 576
#define WAC  (NH*HD)    // 32768
#define BR   80         // B rows for MV gemm: 64 W2T + att1 + att2 + 14 pad
#define DINV 0.125f     // node degree is exactly KD=8 by construction

// ---------------- scratch (static device memory) ----------------
__device__ float g_xpad[NN*FTP];      // tf32-rounded x, padded
__device__ float g_W1T[HD*FTP];       // tf32-rounded W1^T
__device__ float g_W2T[NC*HD];        // tf32-rounded W2^T
__device__ float g_Ball[NH*BR*HD];    // per-head B for MV gemm (rounded)
__device__ float g_BcatT[GC*HD];      // rows 0..511 = M^T (rounded); 512..575 = W2T
__device__ float g_xl[NN*HD];
__device__ float g_ef[EE*HD];
__device__ float g_he[EE*HD];
__device__ float g_featc[NN*HD];      // tf32-rounded feat (A of G gemm)
__device__ float g_V1[HD*NH];
__device__ float g_V2[HD*NH];
__device__ float g_sx[NN*NH];
__device__ float g_se[EE*NH];
__device__ float g_alpha[NNZ*NH];
__device__ float g_G[NN*GC];
__device__ float g_R[EE*HC];
__device__ float g_Y[NN*NC];
__device__ float g_ef2[EE*NC];
__device__ float g_bw2[NC];
__device__ int   g_bcnt[EE];
__device__ int   g_boff[EE];
__device__ int   g_csr[NNZ];
__device__ float g_Binv[EE];

// ---------------- tf32 helpers (arch-portable, sm_80+) ----------------
__device__ __forceinline__ float tf32r(float x) {
    float y;
    asm("cvt.rna.tf32.f32 %0, %1;" : "=f"(y) : "f"(x));
    return y;
}

#define MMA_TF32(C, A0, A1, A2, A3, B0, B1) \
    asm volatile("mma.sync.aligned.m16n8k8.row.col.f32.tf32.tf32.f32 " \
        "{%0,%1,%2,%3},{%4,%5,%6,%7},{%8,%9},{%0,%1,%2,%3};" \
        : "+f"((C)[0]), "+f"((C)[1]), "+f"((C)[2]), "+f"((C)[3]) \
        : "r"(A0), "r"(A1), "r"(A2), "r"(A3), "r"(B0), "r"(B1))

// ============ tf32 mma.sync mainloop: acc += A[128 x 32*NCH] * B[BN x 32*NCH]^T ============
// 256 threads, 8 warps in 4(M) x 2(N). Warp tile: 32 x (BN/2).
template<int BN, int NCH, bool CVTA>
__device__ __forceinline__ void mma_mainloop(const float* __restrict__ A, size_t lda,
                                             const float* __restrict__ B, size_t ldb,
                                             float (&acc)[2][BN/16][4]) {
    constexpr int NT = BN / 16;
    constexpr int PBN = (BN * 16) / 256;      // float2 B loads per thread
    __shared__ float As[128][36];
    __shared__ float Bs[BN][36];
    const int tid = threadIdx.x, lane = tid & 31, wid = tid >> 5;
    const int wm = wid >> 1, wn = wid & 1;
    const int ar = tid >> 3, ac = (tid & 7) * 4;
    const int fr = lane >> 2, fq = lane & 3;
    float4 pa[4];
    float2 pb[PBN];

    // prologue load (chunk 0)
#pragma unroll
    for (int p = 0; p < 4; p++)
        pa[p] = *(const float4*)&A[(size_t)(ar + p * 32) * lda + ac];
#pragma unroll
    for (int p = 0; p < PBN; p++) {
        int idx = tid + p * 256;
        pb[p] = *(const float2*)&B[(size_t)(idx >> 4) * ldb + (idx & 15) * 2];
    }

    for (int c = 0; c < NCH; c++) {
        __syncthreads();
#pragma unroll
        for (int p = 0; p < 4; p++) {
            float4 v = pa[p];
            if (CVTA) { v.x = tf32r(v.x); v.y = tf32r(v.y);
                        v.z = tf32r(v.z); v.w = tf32r(v.w); }
            *(float4*)&As[ar + p * 32][ac] = v;
        }
#pragma unroll
        for (int p = 0; p < PBN; p++) {
            int idx = tid + p * 256;
            *(float2*)&Bs[idx >> 4][(idx & 15) * 2] = pb[p];
        }
        __syncthreads();
        if (c + 1 < NCH) {
            int d0 = (c + 1) * 32;
#pragma unroll
            for (int p = 0; p < 4; p++)
                pa[p] = *(const float4*)&A[(size_t)(ar + p * 32) * lda + d0 + ac];
#pragma unroll
            for (int p = 0; p < PBN; p++) {
                int idx = tid + p * 256;
                pb[p] = *(const float2*)&B[(size_t)(idx >> 4) * ldb + d0 + (idx & 15) * 2];
            }
        }
#pragma unroll
        for (int kk = 0; kk < 4; kk++) {
            int kc = kk * 8 + fq;
            uint32_t afr[2][4];
#pragma unroll
            for (int mt = 0; mt < 2; mt++) {
                int r0 = wm * 32 + mt * 16 + fr;
                afr[mt][0] = __float_as_uint(As[r0][kc]);
                afr[mt][1] = __float_as_uint(As[r0 + 8][kc]);
                afr[mt][2] = __float_as_uint(As[r0][kc + 4]);
                afr[mt][3] = __float_as_uint(As[r0 + 8][kc + 4]);
            }
#pragma unroll
            for (int nt = 0; nt < NT; nt++) {
                int nr = wn * (BN / 2) + nt * 8 + fr;
                uint32_t b0 = __float_as_uint(Bs[nr][kc]);
                uint32_t b1 = __float_as_uint(Bs[nr][kc + 4]);
#pragma unroll
                for (int mt = 0; mt < 2; mt++)
                    MMA_TF32(acc[mt][nt], afr[mt][0], afr[mt][1], afr[mt][2], afr[mt][3], b0, b1);
            }
        }
    }
}

// ---------------- GEMM kernels ----------------
__global__ void __launch_bounds__(256) k_tg1() {       // xl = xpad @ W1T^T
    float acc[2][4][4] = {};
    const float* A = g_xpad + (size_t)blockIdx.x * 128 * FTP;
    const float* B = g_W1T + (size_t)blockIdx.y * 64 * FTP;
    mma_mainloop<64, FTP / 32, false>(A, FTP, B, FTP, acc);
    int lane = threadIdx.x & 31, wid = threadIdx.x >> 5;
    int rb = blockIdx.x * 128 + (wid >> 1) * 32 + (lane >> 2);
    int cb = blockIdx.y * 64 + (wid & 1) * 32 + 2 * (lane & 3);
#pragma unroll
    for (int mt = 0; mt < 2; mt++)
#pragma unroll
        for (int nt = 0; nt < 4; nt++) {
            int r = rb + mt * 16, cc = cb + nt * 8;
            *(float2*)&g_xl[(size_t)r * HD + cc] = make_float2(acc[mt][nt][0], acc[mt][nt][1]);
            *(float2*)&g_xl[(size_t)(r + 8) * HD + cc] = make_float2(acc[mt][nt][2], acc[mt][nt][3]);
        }
}

__global__ void __launch_bounds__(256) k_tgG() {       // G = featc @ BcatT^T
    float acc[2][4][4] = {};
    const float* A = g_featc + (size_t)blockIdx.x * 128 * HD;
    const float* B = g_BcatT + (size_t)blockIdx.y * 64 * HD;
    mma_mainloop<64, HD / 32, false>(A, HD, B, HD, acc);
    int lane = threadIdx.x & 31, wid = threadIdx.x >> 5;
    int rb = blockIdx.x * 128 + (wid >> 1) * 32 + (lane >> 2);
    int cb = blockIdx.y * 64 + (wid & 1) * 32 + 2 * (lane & 3);
#pragma unroll
    for (int mt = 0; mt < 2; mt++)
#pragma unroll
        for (int nt = 0; nt < 4; nt++) {
            int r = rb + mt * 16, cc = cb + nt * 8;
            *(float2*)&g_G[(size_t)r * GC + cc] = make_float2(acc[mt][nt][0], acc[mt][nt][1]);
            *(float2*)&g_G[(size_t)(r + 8) * GC + cc] = make_float2(acc[mt][nt][2], acc[mt][nt][3]);
        }
}

__global__ void __launch_bounds__(256) k_tgMV(const float* __restrict__ Wa) {
    float acc[2][5][4] = {};
    int h = blockIdx.y;
    const float* A = Wa + (size_t)h * HD + (size_t)blockIdx.x * 128 * WAC;
    const float* B = g_Ball + (size_t)h * BR * HD;
    mma_mainloop<80, HD / 32, true>(A, WAC, B, HD, acc);
    int lane = threadIdx.x & 31, wid = threadIdx.x >> 5;
    int k0 = blockIdx.x * 128 + (wid >> 1) * 32 + (lane >> 2);
    int nb = (wid & 1) * 40 + 2 * (lane & 3);
#pragma unroll
    for (int mt = 0; mt < 2; mt++) {
        int k = k0 + mt * 16;
#pragma unroll
        for (int nt = 0; nt < 5; nt++) {
            int n = nb + nt * 8;
            if (n < 64) {
                g_BcatT[(size_t)(h * 64 + n) * HD + k]         = tf32r(acc[mt][nt][0]);
                g_BcatT[(size_t)(h * 64 + n + 1) * HD + k]     = tf32r(acc[mt][nt][1]);
                g_BcatT[(size_t)(h * 64 + n) * HD + k + 8]     = tf32r(acc[mt][nt][2]);
                g_BcatT[(size_t)(h * 64 + n + 1) * HD + k + 8] = tf32r(acc[mt][nt][3]);
            } else if (n == 64) {
                g_V1[k * NH + h]       = acc[mt][nt][0];
                g_V2[k * NH + h]       = acc[mt][nt][1];
                g_V1[(k + 8) * NH + h] = acc[mt][nt][2];
                g_V2[(k + 8) * NH + h] = acc[mt][nt][3];
            }
        }
    }
}

// ---------------- prep kernels (apply tf32 rounding) ----------------
__global__ void k_xpad(const float* __restrict__ x) {
    int i = blockIdx.x * 256 + threadIdx.x;
    if (i < NN * FTP) {
        int r = i / FTP, c = i % FTP;
        g_xpad[i] = (c < FT) ? tf32r(x[r * FT + c]) : 0.0f;
    }
}
__global__ void k_W1T(const float* __restrict__ W1) {   // [FT,HD] -> [HD,FTP], rounded
    __shared__ float t[32][33];
    int kb = blockIdx.y * 32, nb = blockIdx.x * 32;
    int tx = threadIdx.x, ty = threadIdx.y;
    for (int i = ty; i < 32; i += 8) {
        int k = kb + i;
        t[i][tx] = (k < FT) ? tf32r(W1[(size_t)k * HD + nb + tx]) : 0.0f;
    }
    __syncthreads();
    for (int i = ty; i < 32; i += 8)
        g_W1T[(size_t)(nb + i) * FTP + kb + tx] = t[tx][i];
}
__global__ void k_W2T(const float* __restrict__ W2) {   // [HD,NC] -> [NC,HD], rounded
    __shared__ float t[32][33];
    int kb = blockIdx.y * 32, nb = blockIdx.x * 32;
    int tx = threadIdx.x, ty = threadIdx.y;
    for (int i = ty; i < 32; i += 8)
        t[i][tx] = tf32r(W2[(size_t)(kb + i) * NC + nb + tx]);
    __syncthreads();
    for (int i = ty; i < 32; i += 8)
        g_W2T[(size_t)(nb + i) * HD + kb + tx] = t[tx][i];
}
__global__ void k_fillB(const float* __restrict__ att) {
    size_t i = (size_t)blockIdx.x * 256 + threadIdx.x;    // NH*BR*HD
    if (i >= (size_t)NH * BR * HD) return;
    int d = (int)(i & (HD - 1));
    int rh = (int)(i >> 12);
    int r = rh % BR, h = rh / BR;
    float v;
    if (r < 64)       v = g_W2T[(size_t)r * HD + d];
    else if (r == 64) v = tf32r(att[h * 2 * HD + d]);
    else if (r == 65) v = tf32r(att[h * 2 * HD + HD + d]);
    else              v = 0.0f;
    g_Ball[i] = v;
}
__global__ void k_tailB() {                              // BcatT rows 512..575 = W2T
    int i = blockIdx.x * 256 + threadIdx.x;              // NC*HD
    g_BcatT[(size_t)HC * HD + i] = g_W2T[i];
}

// ---------------- degree / CSR ----------------
__global__ void k_zero() {
    g_bcnt[threadIdx.x] = 0;
}
__global__ void k_count(const int* __restrict__ edge) {
    int i = blockIdx.x * blockDim.x + threadIdx.x;
    if (i < NNZ) atomicAdd(&g_bcnt[edge[i]], 1);
}
__global__ void k_scan() {
    __shared__ int s[EE];
    int t = threadIdx.x;
    int v = g_bcnt[t];
    s[t] = v;
    __syncthreads();
    for (int o = 1; o < EE; o <<= 1) {
        int add = (t >= o) ? s[t - o] : 0;
        __syncthreads();
        s[t] += add;
        __syncthreads();
    }
    g_boff[t] = s[t] - v;
    g_Binv[t] = (v > 0) ? 1.0f / (float)v : 0.0f;
}
// warp-per-edge ballot CSR: deterministic (ascending incidence order), parallel
__global__ void __launch_bounds__(1024) k_csr3(const int* __restrict__ edge) {
    __shared__ int se_[NNZ];
    for (int i = threadIdx.x; i < NNZ; i += 1024) se_[i] = edge[i];
    __syncthreads();
    int e = blockIdx.x * 32 + (threadIdx.x >> 5);   // one warp per hyperedge
    int lane = threadIdx.x & 31;
    int w = g_boff[e];
    for (int i = 0; i < NNZ; i += 32) {
        int val = se_[i + lane];
        unsigned mask = __ballot_sync(0xFFFFFFFFu, val == e);
        if (val == e)
            g_csr[w + __popc(mask & ((1u << lane) - 1u))] = i + lane;
        w += __popc(mask);
    }
}

// ---------------- hgc1 gathers (float4) ----------------
__global__ void __launch_bounds__(256) k_edgefeat() {
    int e = blockIdx.x;
    int d4 = blockIdx.y * 256 + threadIdx.x;         // float4 index 0..1023
    int off = g_boff[e], cnt = g_bcnt[e];
    float4 acc = make_float4(0.f, 0.f, 0.f, 0.f);
    const float4* xl4 = (const float4*)g_xl;
    for (int t = 0; t < cnt; t++) {
        int i = g_csr[off + t];
        float4 v = xl4[(size_t)(i >> 3) * (HD / 4) + d4];
        acc.x += v.x; acc.y += v.y; acc.z += v.z; acc.w += v.w;
    }
    float bi = g_Binv[e];
    acc.x *= bi; acc.y *= bi; acc.z *= bi; acc.w *= bi;
    ((float4*)g_ef)[(size_t)e * (HD / 4) + d4] = acc;
}
__global__ void __launch_bounds__(256) k_feat(const int* __restrict__ edge,
                                              const float* __restrict__ b1,
                                              float* __restrict__ feat) {
    int n = blockIdx.x;
    int d4 = blockIdx.y * 256 + threadIdx.x;
    float4 acc = make_float4(0.f, 0.f, 0.f, 0.f);
    const float4* ef4 = (const float4*)g_ef;
#pragma unroll
    for (int j = 0; j < KD; j++) {
        int e = edge[n * KD + j];
        float4 v = ef4[(size_t)e * (HD / 4) + d4];
        acc.x += v.x; acc.y += v.y; acc.z += v.z; acc.w += v.w;
    }
    float4 bb = ((const float4*)b1)[d4];
    float4 r, rc;
    r.x = fmaxf(acc.x * DINV + bb.x, 0.f);
    r.y = fmaxf(acc.y * DINV + bb.y, 0.f);
    r.z = fmaxf(acc.z * DINV + bb.z, 0.f);
    r.w = fmaxf(acc.w * DINV + bb.w, 0.f);
    rc.x = tf32r(r.x); rc.y = tf32r(r.y); rc.z = tf32r(r.z); rc.w = tf32r(r.w);
    ((float4*)feat)[(size_t)n * (HD / 4) + d4] = r;       // exact output #1
    ((float4*)g_featc)[(size_t)n * (HD / 4) + d4] = rc;   // rounded A for G gemm
}
__global__ void __launch_bounds__(256) k_he(const float* __restrict__ feat) {
    int e = blockIdx.x;
    int d4 = blockIdx.y * 256 + threadIdx.x;
    int off = g_boff[e], cnt = g_bcnt[e];
    float4 acc = make_float4(0.f, 0.f, 0.f, 0.f);
    const float4* f4 = (const float4*)feat;
    for (int t = 0; t < cnt; t++) {
        int i = g_csr[off + t];
        float4 v = f4[(size_t)(i >> 3) * (HD / 4) + d4];
        acc.x += v.x; acc.y += v.y; acc.z += v.z; acc.w += v.w;
    }
    float inv = 1.0f / (float)cnt;
    acc.x *= inv; acc.y *= inv; acc.z *= inv; acc.w *= inv;
    ((float4*)g_he)[(size_t)e * (HD / 4) + d4] = acc;
}

// ---------------- attention logits + softmax ----------------
__global__ void __launch_bounds__(256) k_sxse(const float* __restrict__ feat) {
    int b = blockIdx.x;
    const float* row; const float* V; float* out;
    if (b < NN) { row = feat + (size_t)b * HD; V = g_V1; out = g_sx + b * NH; }
    else { int e = b - NN; row = g_he + (size_t)e * HD; V = g_V2; out = g_se + e * NH; }
    float acc[NH] = {};
    for (int k = threadIdx.x; k < HD; k += 256) {
        float xv = row[k];
        float4 w0 = *(const float4*)&V[k * NH];
        float4 w1 = *(const float4*)&V[k * NH + 4];
        acc[0] += xv * w0.x; acc[1] += xv * w0.y; acc[2] += xv * w0.z; acc[3] += xv * w0.w;
        acc[4] += xv * w1.x; acc[5] += xv * w1.y; acc[6] += xv * w1.z; acc[7] += xv * w1.w;
    }
    __shared__ float red[NH][256];
#pragma unroll
    for (int h = 0; h < NH; h++) red[h][threadIdx.x] = acc[h];
    __syncthreads();
    for (int s = 128; s > 0; s >>= 1) {
        if (threadIdx.x < s) {
#pragma unroll
            for (int h = 0; h < NH; h++) red[h][threadIdx.x] += red[h][threadIdx.x + s];
        }
        __syncthreads();
    }
    if (threadIdx.x < NH) out[threadIdx.x] = red[threadIdx.x][0];
}
__global__ void k_alpha(const int* __restrict__ edge) {
    int id = blockIdx.x * blockDim.x + threadIdx.x;
    if (id >= NN * NH) return;
    int n = id >> 3, h = id & 7;
    float sxv = g_sx[n * NH + h];
    float l[KD];
    float m = -1e30f;
#pragma unroll
    for (int j = 0; j < KD; j++) {
        int e = edge[n * KD + j];
        float t = sxv + g_se[e * NH + h];
        t = t > 0.0f ? t : 0.2f * t;
        l[j] = t;
        m = fmaxf(m, t);
    }
    float s = 0.0f;
#pragma unroll
    for (int j = 0; j < KD; j++) { l[j] = expf(l[j] - m); s += l[j]; }
    float inv = 1.0f / s;
#pragma unroll
    for (int j = 0; j < KD; j++) g_alpha[(n * KD + j) * NH + h] = l[j] * inv;
}

// ---------------- CODE-space aggregation ----------------
__global__ void __launch_bounds__(256) k_R() {
    int e = blockIdx.x;
    int hc = blockIdx.y * 256 + threadIdx.x;
    int h = hc >> 6;
    int off = g_boff[e], cnt = g_bcnt[e];
    float acc = 0.0f;
    for (int t = 0; t < cnt; t++) {
        int i = g_csr[off + t];
        acc += g_alpha[i * NH + h] * g_G[(i >> 3) * GC + hc];
    }
    g_R[e * HC + hc] = acc * g_Binv[e];
}
__global__ void k_bw2(const float* __restrict__ ba, const float* __restrict__ W2) {
    int tid = threadIdx.x;
    int c = tid & 63, sl = tid >> 6;
    float acc = 0.0f;
    for (int d = sl * 1024; d < (sl + 1) * 1024; d++) acc += ba[d] * W2[d * NC + c];
    __shared__ float r[256];
    r[tid] = acc;
    __syncthreads();
    if (sl == 0) g_bw2[c] = r[c] + r[c + 64] + r[c + 128] + r[c + 192];
}
__global__ void k_Y(const int* __restrict__ edge) {
    int n = blockIdx.x, c = threadIdx.x;
    float acc = g_G[n * GC + HC + c] + g_bw2[c];
    float s = 0.0f;
#pragma unroll
    for (int j = 0; j < KD; j++) {
        int e = edge[n * KD + j];
        const float* al = &g_alpha[(n * KD + j) * NH];
        const float* Rr = &g_R[e * HC + c];
#pragma unroll
        for (int h = 0; h < NH; h++) s += al[h] * Rr[h * NC];
    }
    g_Y[n * NC + c] = acc + s * DINV * (1.0f / NH);
}
__global__ void k_ef2() {
    int e = blockIdx.x, c = threadIdx.x;
    int off = g_boff[e], cnt = g_bcnt[e];
    float acc = 0.0f;
    for (int t = 0; t < cnt; t++) {
        int i = g_csr[off + t];
        acc += g_Y[(i >> 3) * NC + c];
    }
    g_ef2[e * NC + c] = acc * g_Binv[e];
}
__global__ void k_out(const int* __restrict__ edge, const float* __restrict__ b2,
                      float* __restrict__ out) {
    int n = blockIdx.x, c = threadIdx.x;
    float acc = 0.0f;
#pragma unroll
    for (int j = 0; j < KD; j++) {
        int e = edge[n * KD + j];
        acc += g_ef2[e * NC + c];
    }
    float hid = acc * DINV + b2[c];
    out[(size_t)NN * HD + n * NC + c] = hid;
    out[(size_t)NN * HD + NN * NC + n * NC + c] = tanhf(hid);
}

// ---------------- launch ----------------
extern "C" void kernel_launch(void* const* d_in, const int* in_sizes, int n_in,
                              void* d_out, int out_size) {
    const float* x    = (const float*)d_in[0];
    const int*   edge = (const int*)  d_in[2];
    const float* W1   = (const float*)d_in[3];
    const float* b1   = (const float*)d_in[4];
    const float* Wa   = (const float*)d_in[5];
    const float* att  = (const float*)d_in[6];
    const float* ba   = (const float*)d_in[7];
    const float* W2   = (const float*)d_in[8];
    const float* b2   = (const float*)d_in[9];
    float* out  = (float*)d_out;
    float* feat = out;

    k_zero<<<1, 512>>>();
    k_count<<<16, 256>>>(edge);
    k_scan<<<1, 512>>>();
    k_csr3<<<16, 1024>>>(edge);

    k_xpad<<<(NN * FTP + 255) / 256, 256>>>(x);
    k_W1T<<<dim3(HD / 32, FTP / 32), dim3(32, 8)>>>(W1);
    k_W2T<<<dim3(NC / 32, HD / 32), dim3(32, 8)>>>(W2);
    k_fillB<<<(NH * BR * HD + 255) / 256, 256>>>(att);
    k_tailB<<<(NC * HD) / 256, 256>>>();

    k_tg1<<<dim3(4, 64), 256>>>();                       // xl = x @ W1 (tf32)
    k_edgefeat<<<dim3(EE, 4), 256>>>();
    k_feat<<<dim3(NN, 4), 256>>>(edge, b1, feat);
    k_he<<<dim3(EE, 4), 256>>>(feat);

    k_tgMV<<<dim3(32, 8), 256>>>(Wa);                    // M^T -> BcatT, V1/V2 (tf32)

    k_sxse<<<NN + EE, 256>>>(feat);
    k_alpha<<<16, 256>>>(edge);

    k_tgG<<<dim3(4, 9), 256>>>();                        // G = feat @ [M | W2] (tf32)
    k_R<<<dim3(EE, 2), 256>>>();
    k_bw2<<<1, 256>>>(ba, W2);
    k_Y<<<NN, 64>>>(edge);

    k_ef2<<<EE, 64>>>();
    k_out<<<NN, 64>>>(edge, b2, out);
}

// round 5
// speedup vs baseline: 2.5839x; 1.0815x over previous
#include <cuda_runtime.h>
#include <math.h>
#include <stdint.h>

#define NN   512        // nodes
#define KD   8          // edges per node
#define NNZ  4096       // incidences
#define FT   1386       // text features
#define FTP  1408       // padded to 32-multiple
#define HD   4096       // hidden
#define NH   8          // heads
#define NC   64         // code
#define EE   512        // hyperedges
#define HC   (NH*NC)    // 512
#define GC   (HC+NC)    // 576
#define WAC  (NH*HD)    // 32768
#define BR   80         // B rows for MV gemm: 64 W2T + att1 + att2 + 14 pad
#define DINV 0.125f     // node degree is exactly KD=8 by construction

// ---------------- scratch (static device memory) ----------------
__device__ float g_xpad[NN*FTP];      // tf32-rounded x, padded
__device__ float g_W1T[HD*FTP];       // tf32-rounded W1^T
__device__ float g_W2T[NC*HD];        // tf32-rounded W2^T
__device__ float g_Ball[NH*BR*HD];    // per-head B for MV gemm (rounded)
__device__ float g_BcatT[GC*HD];      // rows 0..511 = M^T; 512..575 = W2T
__device__ float g_xl[NN*HD];
__device__ float g_ef[EE*HD];
__device__ float g_he[EE*HD];
__device__ float g_V1[HD*NH];
__device__ float g_V2[HD*NH];
__device__ float g_sx[NN*NH];
__device__ float g_se[EE*NH];
__device__ float g_alpha[NNZ*NH];
__device__ float g_G[NN*GC];
__device__ float g_R[EE*HC];
__device__ float g_Y[NN*NC];
__device__ float g_ef2[EE*NC];
__device__ float g_bw2[NC];
__device__ int   g_bcnt[EE];
__device__ int   g_boff[EE];
__device__ int   g_csr[NNZ];
__device__ float g_Binv[EE];

// ---------------- tf32 helpers (arch-portable, sm_80+) ----------------
__device__ __forceinline__ float tf32r(float x) {
    float y;
    asm("cvt.rna.tf32.f32 %0, %1;" : "=f"(y) : "f"(x));
    return y;
}

#define MMA_TF32(C, A0, A1, A2, A3, B0, B1) \
    asm volatile("mma.sync.aligned.m16n8k8.row.col.f32.tf32.tf32.f32 " \
        "{%0,%1,%2,%3},{%4,%5,%6,%7},{%8,%9},{%0,%1,%2,%3};" \
        : "+f"((C)[0]), "+f"((C)[1]), "+f"((C)[2]), "+f"((C)[3]) \
        : "r"(A0), "r"(A1), "r"(A2), "r"(A3), "r"(B0), "r"(B1))

// ============ tf32 mma.sync mainloop: acc += A[128 x 32*NCH] * B[BN x 32*NCH]^T ============
// 256 threads, 8 warps in 4(M) x 2(N). Warp tile: 32 x (BN/2).
template<int BN, int NCH, bool CVTA>
__device__ __forceinline__ void mma_mainloop(const float* __restrict__ A, size_t lda,
                                             const float* __restrict__ B, size_t ldb,
                                             float (&acc)[2][BN/16][4]) {
    constexpr int NT = BN / 16;
    constexpr int PBN = (BN * 16) / 256;      // float2 B loads per thread
    __shared__ float As[128][36];
    __shared__ float Bs[BN][36];
    const int tid = threadIdx.x, lane = tid & 31, wid = tid >> 5;
    const int wm = wid >> 1, wn = wid & 1;
    const int ar = tid >> 3, ac = (tid & 7) * 4;
    const int fr = lane >> 2, fq = lane & 3;
    float4 pa[4];
    float2 pb[PBN];

    // prologue load (chunk 0)
#pragma unroll
    for (int p = 0; p < 4; p++)
        pa[p] = *(const float4*)&A[(size_t)(ar + p * 32) * lda + ac];
#pragma unroll
    for (int p = 0; p < PBN; p++) {
        int idx = tid + p * 256;
        pb[p] = *(const float2*)&B[(size_t)(idx >> 4) * ldb + (idx & 15) * 2];
    }

    for (int c = 0; c < NCH; c++) {
        __syncthreads();
#pragma unroll
        for (int p = 0; p < 4; p++) {
            float4 v = pa[p];
            if (CVTA) { v.x = tf32r(v.x); v.y = tf32r(v.y);
                        v.z = tf32r(v.z); v.w = tf32r(v.w); }
            *(float4*)&As[ar + p * 32][ac] = v;
        }
#pragma unroll
        for (int p = 0; p < PBN; p++) {
            int idx = tid + p * 256;
            *(float2*)&Bs[idx >> 4][(idx & 15) * 2] = pb[p];
        }
        __syncthreads();
        if (c + 1 < NCH) {
            int d0 = (c + 1) * 32;
#pragma unroll
            for (int p = 0; p < 4; p++)
                pa[p] = *(const float4*)&A[(size_t)(ar + p * 32) * lda + d0 + ac];
#pragma unroll
            for (int p = 0; p < PBN; p++) {
                int idx = tid + p * 256;
                pb[p] = *(const float2*)&B[(size_t)(idx >> 4) * ldb + d0 + (idx & 15) * 2];
            }
        }
#pragma unroll
        for (int kk = 0; kk < 4; kk++) {
            int kc = kk * 8 + fq;
            uint32_t afr[2][4];
#pragma unroll
            for (int mt = 0; mt < 2; mt++) {
                int r0 = wm * 32 + mt * 16 + fr;
                afr[mt][0] = __float_as_uint(As[r0][kc]);
                afr[mt][1] = __float_as_uint(As[r0 + 8][kc]);
                afr[mt][2] = __float_as_uint(As[r0][kc + 4]);
                afr[mt][3] = __float_as_uint(As[r0 + 8][kc + 4]);
            }
#pragma unroll
            for (int nt = 0; nt < NT; nt++) {
                int nr = wn * (BN / 2) + nt * 8 + fr;
                uint32_t b0 = __float_as_uint(Bs[nr][kc]);
                uint32_t b1 = __float_as_uint(Bs[nr][kc + 4]);
#pragma unroll
                for (int mt = 0; mt < 2; mt++)
                    MMA_TF32(acc[mt][nt], afr[mt][0], afr[mt][1], afr[mt][2], afr[mt][3], b0, b1);
            }
        }
    }
}

// ---------------- GEMM kernels ----------------
__global__ void __launch_bounds__(256) k_tg1() {       // xl = xpad @ W1T^T
    float acc[2][4][4] = {};
    const float* A = g_xpad + (size_t)blockIdx.x * 128 * FTP;
    const float* B = g_W1T + (size_t)blockIdx.y * 64 * FTP;
    mma_mainloop<64, FTP / 32, false>(A, FTP, B, FTP, acc);
    int lane = threadIdx.x & 31, wid = threadIdx.x >> 5;
    int rb = blockIdx.x * 128 + (wid >> 1) * 32 + (lane >> 2);
    int cb = blockIdx.y * 64 + (wid & 1) * 32 + 2 * (lane & 3);
#pragma unroll
    for (int mt = 0; mt < 2; mt++)
#pragma unroll
        for (int nt = 0; nt < 4; nt++) {
            int r = rb + mt * 16, cc = cb + nt * 8;
            *(float2*)&g_xl[(size_t)r * HD + cc] = make_float2(acc[mt][nt][0], acc[mt][nt][1]);
            *(float2*)&g_xl[(size_t)(r + 8) * HD + cc] = make_float2(acc[mt][nt][2], acc[mt][nt][3]);
        }
}

__global__ void __launch_bounds__(256) k_tgG(const float* __restrict__ feat) {
    float acc[2][4][4] = {};
    const float* A = feat + (size_t)blockIdx.x * 128 * HD;
    const float* B = g_BcatT + (size_t)blockIdx.y * 64 * HD;
    mma_mainloop<64, HD / 32, true>(A, HD, B, HD, acc);   // round A in-register
    int lane = threadIdx.x & 31, wid = threadIdx.x >> 5;
    int rb = blockIdx.x * 128 + (wid >> 1) * 32 + (lane >> 2);
    int cb = blockIdx.y * 64 + (wid & 1) * 32 + 2 * (lane & 3);
#pragma unroll
    for (int mt = 0; mt < 2; mt++)
#pragma unroll
        for (int nt = 0; nt < 4; nt++) {
            int r = rb + mt * 16, cc = cb + nt * 8;
            *(float2*)&g_G[(size_t)r * GC + cc] = make_float2(acc[mt][nt][0], acc[mt][nt][1]);
            *(float2*)&g_G[(size_t)(r + 8) * GC + cc] = make_float2(acc[mt][nt][2], acc[mt][nt][3]);
        }
}

__global__ void __launch_bounds__(256) k_tgMV(const float* __restrict__ Wa) {
    float acc[2][5][4] = {};
    int h = blockIdx.y;
    const float* A = Wa + (size_t)h * HD + (size_t)blockIdx.x * 128 * WAC;
    const float* B = g_Ball + (size_t)h * BR * HD;
    mma_mainloop<80, HD / 32, true>(A, WAC, B, HD, acc);
    int lane = threadIdx.x & 31, wid = threadIdx.x >> 5;
    int k0 = blockIdx.x * 128 + (wid >> 1) * 32 + (lane >> 2);
    int nb = (wid & 1) * 40 + 2 * (lane & 3);
#pragma unroll
    for (int mt = 0; mt < 2; mt++) {
        int k = k0 + mt * 16;
#pragma unroll
        for (int nt = 0; nt < 5; nt++) {
            int n = nb + nt * 8;
            if (n < 64) {
                g_BcatT[(size_t)(h * 64 + n) * HD + k]         = tf32r(acc[mt][nt][0]);
                g_BcatT[(size_t)(h * 64 + n + 1) * HD + k]     = tf32r(acc[mt][nt][1]);
                g_BcatT[(size_t)(h * 64 + n) * HD + k + 8]     = tf32r(acc[mt][nt][2]);
                g_BcatT[(size_t)(h * 64 + n + 1) * HD + k + 8] = tf32r(acc[mt][nt][3]);
            } else if (n == 64) {
                g_V1[k * NH + h]       = acc[mt][nt][0];
                g_V2[k * NH + h]       = acc[mt][nt][1];
                g_V1[(k + 8) * NH + h] = acc[mt][nt][2];
                g_V2[(k + 8) * NH + h] = acc[mt][nt][3];
            }
        }
    }
}

// ---------------- fused prep: xpad | W1T | W2T(+BcatT tail) | bw2 ----------------
#define NB_XPAD (NN*FTP/256)          // 2816
#define NB_W1T  ((FTP/32)*(HD/32))    // 5632
#define NB_W2T  ((HD/32)*(NC/32))     // 256
__global__ void __launch_bounds__(256) k_prepA(const float* __restrict__ x,
                                               const float* __restrict__ W1,
                                               const float* __restrict__ W2,
                                               const float* __restrict__ ba) {
    __shared__ float t[32][33];
    __shared__ float red[256];
    int b = blockIdx.x, tid = threadIdx.x;
    if (b < NB_XPAD) {                                   // ---- xpad ----
        int i = b * 256 + tid;
        int r = i / FTP, c = i % FTP;
        g_xpad[i] = (c < FT) ? tf32r(x[r * FT + c]) : 0.0f;
        return;
    }
    b -= NB_XPAD;
    if (b < NB_W1T) {                                    // ---- W1T transpose ----
        int ky = b / (HD / 32), nx = b % (HD / 32);
        int kb = ky * 32, nb = nx * 32;
        int tx = tid & 31, ty = tid >> 5;
        for (int i = ty; i < 32; i += 8) {
            int k = kb + i;
            t[i][tx] = (k < FT) ? tf32r(W1[(size_t)k * HD + nb + tx]) : 0.0f;
        }
        __syncthreads();
        for (int i = ty; i < 32; i += 8)
            g_W1T[(size_t)(nb + i) * FTP + kb + tx] = t[tx][i];
        return;
    }
    b -= NB_W1T;
    if (b < NB_W2T) {                                    // ---- W2T + BcatT tail ----
        int kb = (b >> 1) * 32, nb = (b & 1) * 32;
        int tx = tid & 31, ty = tid >> 5;
        for (int i = ty; i < 32; i += 8)
            t[i][tx] = tf32r(W2[(size_t)(kb + i) * NC + nb + tx]);
        __syncthreads();
        for (int i = ty; i < 32; i += 8) {
            float v = t[tx][i];
            g_W2T[(size_t)(nb + i) * HD + kb + tx] = v;
            g_BcatT[(size_t)(HC + nb + i) * HD + kb + tx] = v;
        }
        return;
    }
    // ---- bw2 = ba @ W2 (1 block) ----
    int c = tid & 63, sl = tid >> 6;
    float acc = 0.0f;
    for (int d = sl * 1024; d < (sl + 1) * 1024; d++) acc += ba[d] * W2[d * NC + c];
    red[tid] = acc;
    __syncthreads();
    if (sl == 0) g_bw2[c] = red[c] + red[c + 64] + red[c + 128] + red[c + 192];
}

__global__ void k_fillB(const float* __restrict__ att) {
    size_t i = (size_t)blockIdx.x * 256 + threadIdx.x;    // NH*BR*HD
    if (i >= (size_t)NH * BR * HD) return;
    int d = (int)(i & (HD - 1));
    int rh = (int)(i >> 12);
    int r = rh % BR, h = rh / BR;
    float v;
    if (r < 64)       v = g_W2T[(size_t)r * HD + d];
    else if (r == 64) v = tf32r(att[h * 2 * HD + d]);
    else if (r == 65) v = tf32r(att[h * 2 * HD + HD + d]);
    else              v = 0.0f;
    g_Ball[i] = v;
}

// ---------------- fused CSR: per-warp count + offset + place (deterministic) ----------------
__global__ void __launch_bounds__(256) k_csr(const int* __restrict__ edge) {
    __shared__ int se_[NNZ];
    int tid = threadIdx.x;
    for (int i = tid; i < NNZ; i += 256) se_[i] = edge[i];
    __syncthreads();
    int lane = tid & 31;
    int e = blockIdx.x * 8 + (tid >> 5);     // one warp per hyperedge
    int nlt = 0, cnt = 0;
    for (int i = lane; i < NNZ; i += 32) {
        int v = se_[i];
        nlt += __popc(__ballot_sync(0xFFFFFFFFu, v < e));
        cnt += __popc(__ballot_sync(0xFFFFFFFFu, v == e));
    }
    int w = nlt;                              // boff[e] = #{values < e}
    for (int i = lane; i < NNZ; i += 32) {
        int v = se_[i];
        unsigned m = __ballot_sync(0xFFFFFFFFu, v == e);
        if (v == e)
            g_csr[w + __popc(m & ((1u << lane) - 1u))] = i;
        w += __popc(m);
    }
    if (lane == 0) {
        g_bcnt[e] = cnt;
        g_boff[e] = nlt;
        g_Binv[e] = (cnt > 0) ? 1.0f / (float)cnt : 0.0f;
    }
}

// ---------------- hgc1 gathers (float4) ----------------
__global__ void __launch_bounds__(256) k_edgefeat() {
    int e = blockIdx.x;
    int d4 = blockIdx.y * 256 + threadIdx.x;
    int off = g_boff[e], cnt = g_bcnt[e];
    float4 acc = make_float4(0.f, 0.f, 0.f, 0.f);
    const float4* xl4 = (const float4*)g_xl;
    for (int t = 0; t < cnt; t++) {
        int i = g_csr[off + t];
        float4 v = xl4[(size_t)(i >> 3) * (HD / 4) + d4];
        acc.x += v.x; acc.y += v.y; acc.z += v.z; acc.w += v.w;
    }
    float bi = g_Binv[e];
    acc.x *= bi; acc.y *= bi; acc.z *= bi; acc.w *= bi;
    ((float4*)g_ef)[(size_t)e * (HD / 4) + d4] = acc;
}
__global__ void __launch_bounds__(256) k_feat(const int* __restrict__ edge,
                                              const float* __restrict__ b1,
                                              float* __restrict__ feat) {
    int n = blockIdx.x;
    int d4 = blockIdx.y * 256 + threadIdx.x;
    float4 acc = make_float4(0.f, 0.f, 0.f, 0.f);
    const float4* ef4 = (const float4*)g_ef;
#pragma unroll
    for (int j = 0; j < KD; j++) {
        int e = edge[n * KD + j];
        float4 v = ef4[(size_t)e * (HD / 4) + d4];
        acc.x += v.x; acc.y += v.y; acc.z += v.z; acc.w += v.w;
    }
    float4 bb = ((const float4*)b1)[d4];
    float4 r;
    r.x = fmaxf(acc.x * DINV + bb.x, 0.f);
    r.y = fmaxf(acc.y * DINV + bb.y, 0.f);
    r.z = fmaxf(acc.z * DINV + bb.z, 0.f);
    r.w = fmaxf(acc.w * DINV + bb.w, 0.f);
    ((float4*)feat)[(size_t)n * (HD / 4) + d4] = r;       // exact output #1
}
__global__ void __launch_bounds__(256) k_he(const float* __restrict__ feat) {
    int e = blockIdx.x;
    int d4 = blockIdx.y * 256 + threadIdx.x;
    int off = g_boff[e], cnt = g_bcnt[e];
    float4 acc = make_float4(0.f, 0.f, 0.f, 0.f);
    const float4* f4 = (const float4*)feat;
    for (int t = 0; t < cnt; t++) {
        int i = g_csr[off + t];
        float4 v = f4[(size_t)(i >> 3) * (HD / 4) + d4];
        acc.x += v.x; acc.y += v.y; acc.z += v.z; acc.w += v.w;
    }
    float inv = 1.0f / (float)cnt;
    acc.x *= inv; acc.y *= inv; acc.z *= inv; acc.w *= inv;
    ((float4*)g_he)[(size_t)e * (HD / 4) + d4] = acc;
}

// ---------------- attention logits + softmax ----------------
__global__ void __launch_bounds__(256) k_sxse(const float* __restrict__ feat) {
    int b = blockIdx.x;
    const float* row; const float* V; float* out;
    if (b < NN) { row = feat + (size_t)b * HD; V = g_V1; out = g_sx + b * NH; }
    else { int e = b - NN; row = g_he + (size_t)e * HD; V = g_V2; out = g_se + e * NH; }
    float acc[NH] = {};
    for (int k = threadIdx.x; k < HD; k += 256) {
        float xv = row[k];
        float4 w0 = *(const float4*)&V[k * NH];
        float4 w1 = *(const float4*)&V[k * NH + 4];
        acc[0] += xv * w0.x; acc[1] += xv * w0.y; acc[2] += xv * w0.z; acc[3] += xv * w0.w;
        acc[4] += xv * w1.x; acc[5] += xv * w1.y; acc[6] += xv * w1.z; acc[7] += xv * w1.w;
    }
    __shared__ float red[NH][256];
#pragma unroll
    for (int h = 0; h < NH; h++) red[h][threadIdx.x] = acc[h];
    __syncthreads();
    for (int s = 128; s > 0; s >>= 1) {
        if (threadIdx.x < s) {
#pragma unroll
            for (int h = 0; h < NH; h++) red[h][threadIdx.x] += red[h][threadIdx.x + s];
        }
        __syncthreads();
    }
    if (threadIdx.x < NH) out[threadIdx.x] = red[threadIdx.x][0];
}
__global__ void k_alpha(const int* __restrict__ edge) {
    int id = blockIdx.x * blockDim.x + threadIdx.x;
    if (id >= NN * NH) return;
    int n = id >> 3, h = id & 7;
    float sxv = g_sx[n * NH + h];
    float l[KD];
    float m = -1e30f;
#pragma unroll
    for (int j = 0; j < KD; j++) {
        int e = edge[n * KD + j];
        float t = sxv + g_se[e * NH + h];
        t = t > 0.0f ? t : 0.2f * t;
        l[j] = t;
        m = fmaxf(m, t);
    }
    float s = 0.0f;
#pragma unroll
    for (int j = 0; j < KD; j++) { l[j] = expf(l[j] - m); s += l[j]; }
    float inv = 1.0f / s;
#pragma unroll
    for (int j = 0; j < KD; j++) g_alpha[(n * KD + j) * NH + h] = l[j] * inv;
}

// ---------------- CODE-space aggregation ----------------
__global__ void __launch_bounds__(256) k_R() {
    int e = blockIdx.x;
    int hc = blockIdx.y * 256 + threadIdx.x;
    int h = hc >> 6;
    int off = g_boff[e], cnt = g_bcnt[e];
    float acc = 0.0f;
    for (int t = 0; t < cnt; t++) {
        int i = g_csr[off + t];
        acc += g_alpha[i * NH + h] * g_G[(i >> 3) * GC + hc];
    }
    g_R[e * HC + hc] = acc * g_Binv[e];
}
__global__ void k_Y(const int* __restrict__ edge) {
    int n = blockIdx.x, c = threadIdx.x;
    float acc = g_G[n * GC + HC + c] + g_bw2[c];
    float s = 0.0f;
#pragma unroll
    for (int j = 0; j < KD; j++) {
        int e = edge[n * KD + j];
        const float* al = &g_alpha[(n * KD + j) * NH];
        const float* Rr = &g_R[e * HC + c];
#pragma unroll
        for (int h = 0; h < NH; h++) s += al[h] * Rr[h * NC];
    }
    g_Y[n * NC + c] = acc + s * DINV * (1.0f / NH);
}
__global__ void k_ef2() {
    int e = blockIdx.x, c = threadIdx.x;
    int off = g_boff[e], cnt = g_bcnt[e];
    float acc = 0.0f;
    for (int t = 0; t < cnt; t++) {
        int i = g_csr[off + t];
        acc += g_Y[(i >> 3) * NC + c];
    }
    g_ef2[e * NC + c] = acc * g_Binv[e];
}
__global__ void k_out(const int* __restrict__ edge, const float* __restrict__ b2,
                      float* __restrict__ out) {
    int n = blockIdx.x, c = threadIdx.x;
    float acc = 0.0f;
#pragma unroll
    for (int j = 0; j < KD; j++) {
        int e = edge[n * KD + j];
        acc += g_ef2[e * NC + c];
    }
    float hid = acc * DINV + b2[c];
    out[(size_t)NN * HD + n * NC + c] = hid;
    out[(size_t)NN * HD + NN * NC + n * NC + c] = tanhf(hid);
}

// ---------------- launch ----------------
extern "C" void kernel_launch(void* const* d_in, const int* in_sizes, int n_in,
                              void* d_out, int out_size) {
    const float* x    = (const float*)d_in[0];
    const int*   edge = (const int*)  d_in[2];
    const float* W1   = (const float*)d_in[3];
    const float* b1   = (const float*)d_in[4];
    const float* Wa   = (const float*)d_in[5];
    const float* att  = (const float*)d_in[6];
    const float* ba   = (const float*)d_in[7];
    const float* W2   = (const float*)d_in[8];
    const float* b2   = (const float*)d_in[9];
    float* out  = (float*)d_out;
    float* feat = out;

    k_csr<<<64, 256>>>(edge);                                 // 1
    k_prepA<<<NB_XPAD + NB_W1T + NB_W2T + 1, 256>>>(x, W1, W2, ba); // 2
    k_fillB<<<(NH * BR * HD + 255) / 256, 256>>>(att);        // 3
    k_tg1<<<dim3(4, 64), 256>>>();                            // 4
    k_edgefeat<<<dim3(EE, 4), 256>>>();                       // 5
    k_tgMV<<<dim3(32, 8), 256>>>(Wa);                         // 6  <- ncu -s 5 lands here
    k_feat<<<dim3(NN, 4), 256>>>(edge, b1, feat);             // 7
    k_he<<<dim3(EE, 4), 256>>>(feat);                         // 8
    k_sxse<<<NN + EE, 256>>>(feat);                           // 9
    k_alpha<<<16, 256>>>(edge);                               // 10
    k_tgG<<<dim3(4, 9), 256>>>(feat);                         // 11
    k_R<<<dim3(EE, 2), 256>>>();                              // 12
    k_Y<<<NN, 64>>>(edge);                                    // 13
    k_ef2<<<EE, 64>>>();                                      // 14
    k_out<<<NN, 64>>>(edge, b2, out);                         // 15
}

// round 6
// speedup vs baseline: 3.0483x; 1.1797x over previous
#include <cuda_runtime.h>
#include <math.h>
#include <stdint.h>

#define NN   512        // nodes
#define KD   8          // edges per node
#define NNZ  4096       // incidences
#define FT   1386       // text features
#define FTP  1408       // padded to 32-multiple
#define HD   4096       // hidden
#define NH   8          // heads
#define NC   64         // code
#define EE   512        // hyperedges
#define HC   (NH*NC)    // 512
#define GC   (HC+NC)    // 576
#define WAC  (NH*HD)    // 32768
#define BR   80         // B rows for MV gemm: 64 W2T + att1 + att2 + 14 pad
#define DINV 0.125f     // node degree is exactly KD=8 by construction

// ---------------- scratch (static device memory) ----------------
__device__ float g_xpad[NN*FTP];      // tf32-rounded x, padded
__device__ float g_W1T[HD*FTP];       // tf32-rounded W1^T
__device__ float g_W2T[NC*HD];        // tf32-rounded W2^T
__device__ float g_Ball[NH*BR*HD];    // per-head B for MV gemm (rounded)
__device__ float g_BcatT[GC*HD];      // rows 0..511 = M^T; 512..575 = W2T
__device__ float g_xl[NN*HD];
__device__ float g_ef[EE*HD];
__device__ float g_he[EE*HD];
__device__ float g_featc[NN*HD];      // tf32-rounded feat (A of G gemm)
__device__ float g_V1[HD*NH];
__device__ float g_V2[HD*NH];
__device__ float g_sx[NN*NH];
__device__ float g_se[EE*NH];
__device__ float g_alpha[NNZ*NH];
__device__ float g_G[NN*GC];
__device__ float g_R[EE*HC];
__device__ float g_Y[NN*NC];
__device__ float g_ef2[EE*NC];
__device__ float g_bw2[NC];
__device__ int   g_bcnt[EE];
__device__ int   g_boff[EE];
__device__ int   g_csr[NNZ];
__device__ float g_Binv[EE];

// ---------------- helpers ----------------
__device__ __forceinline__ float tf32r(float x) {
    float y;
    asm("cvt.rna.tf32.f32 %0, %1;" : "=f"(y) : "f"(x));
    return y;
}
__device__ __forceinline__ uint32_t smem_u32(const void* p) {
    uint32_t a;
    asm("{ .reg .u64 t; cvta.to.shared.u64 t, %1; cvt.u32.u64 %0, t; }" : "=r"(a) : "l"(p));
    return a;
}
#define CP_ASYNC16(dst, src) \
    asm volatile("cp.async.cg.shared.global [%0], [%1], 16;" :: "r"(dst), "l"(src))
#define CP_COMMIT() asm volatile("cp.async.commit_group;" ::: "memory")
#define CP_WAIT1()  asm volatile("cp.async.wait_group 1;" ::: "memory")
#define CP_WAIT0()  asm volatile("cp.async.wait_group 0;" ::: "memory")

#define MMA_TF32(C, A0, A1, A2, A3, B0, B1) \
    asm volatile("mma.sync.aligned.m16n8k8.row.col.f32.tf32.tf32.f32 " \
        "{%0,%1,%2,%3},{%4,%5,%6,%7},{%8,%9},{%0,%1,%2,%3};" \
        : "+f"((C)[0]), "+f"((C)[1]), "+f"((C)[2]), "+f"((C)[3]) \
        : "r"(A0), "r"(A1), "r"(A2), "r"(A3), "r"(B0), "r"(B1))

// ============ tf32 mma.sync mainloop, cp.async A pipeline ============
// C[128 x BN] += A[128 x 32*NCH] * B[BN x 32*NCH]^T
// 256 threads, 8 warps in 4(M) x 2(N). A: 2-stage cp.async; B: reg prefetch.
template<int BN, int NCH>
__device__ __forceinline__ void mma_mainloop(const float* __restrict__ A, size_t lda,
                                             const float* __restrict__ B, size_t ldb,
                                             float (&acc)[2][BN/16][4]) {
    constexpr int NT = BN / 16;
    constexpr int PBN = (BN * 16) / 256;      // float2 B loads per thread
    __shared__ __align__(16) float As[2][128][36];
    __shared__ __align__(16) float Bs[BN][36];
    const int tid = threadIdx.x, lane = tid & 31, wid = tid >> 5;
    const int wm = wid >> 1, wn = wid & 1;
    const int ar = tid >> 3, ac = (tid & 7) * 4;
    const int fr = lane >> 2, fq = lane & 3;
    const uint32_t aBase = smem_u32(&As[0][0][0]);
    float2 pb[PBN];

    // prologue: A chunk 0 via cp.async, B chunk 0 into regs
#pragma unroll
    for (int p = 0; p < 4; p++) {
        uint32_t dst = aBase + (uint32_t)(((ar + p * 32) * 36 + ac) * 4);
        CP_ASYNC16(dst, A + (size_t)(ar + p * 32) * lda + ac);
    }
    CP_COMMIT();
#pragma unroll
    for (int p = 0; p < PBN; p++) {
        int idx = tid + p * 256;
        pb[p] = *(const float2*)&B[(size_t)(idx >> 4) * ldb + (idx & 15) * 2];
    }

    for (int c = 0; c < NCH; c++) {
        __syncthreads();                       // prior compute done: Bs + stage (c+1)&1 free
        if (c + 1 < NCH) {                     // issue A chunk c+1
            uint32_t sB = aBase + ((c + 1) & 1) * (128 * 36 * 4);
            int d0 = (c + 1) * 32;
#pragma unroll
            for (int p = 0; p < 4; p++) {
                uint32_t dst = sB + (uint32_t)(((ar + p * 32) * 36 + ac) * 4);
                CP_ASYNC16(dst, A + (size_t)(ar + p * 32) * lda + d0 + ac);
            }
            CP_COMMIT();
        }
        // store B chunk c from regs
#pragma unroll
        for (int p = 0; p < PBN; p++) {
            int idx = tid + p * 256;
            *(float2*)&Bs[idx >> 4][(idx & 15) * 2] = pb[p];
        }
        if (c + 1 < NCH) CP_WAIT1(); else CP_WAIT0();   // A chunk c arrived
        __syncthreads();
        if (c + 1 < NCH) {                     // prefetch B chunk c+1 (overlaps compute)
            int d0 = (c + 1) * 32;
#pragma unroll
            for (int p = 0; p < PBN; p++) {
                int idx = tid + p * 256;
                pb[p] = *(const float2*)&B[(size_t)(idx >> 4) * ldb + d0 + (idx & 15) * 2];
            }
        }
        const int s = c & 1;
#pragma unroll
        for (int kk = 0; kk < 4; kk++) {
            int kc = kk * 8 + fq;
            uint32_t afr[2][4];
#pragma unroll
            for (int mt = 0; mt < 2; mt++) {
                int r0 = wm * 32 + mt * 16 + fr;
                afr[mt][0] = __float_as_uint(As[s][r0][kc]);
                afr[mt][1] = __float_as_uint(As[s][r0 + 8][kc]);
                afr[mt][2] = __float_as_uint(As[s][r0][kc + 4]);
                afr[mt][3] = __float_as_uint(As[s][r0 + 8][kc + 4]);
            }
#pragma unroll
            for (int nt = 0; nt < NT; nt++) {
                int nr = wn * (BN / 2) + nt * 8 + fr;
                uint32_t b0 = __float_as_uint(Bs[nr][kc]);
                uint32_t b1 = __float_as_uint(Bs[nr][kc + 4]);
#pragma unroll
                for (int mt = 0; mt < 2; mt++)
                    MMA_TF32(acc[mt][nt], afr[mt][0], afr[mt][1], afr[mt][2], afr[mt][3], b0, b1);
            }
        }
    }
}

// ---------------- GEMM kernels ----------------
__global__ void __launch_bounds__(256, 3) k_tg1() {       // xl = xpad @ W1T^T
    float acc[2][4][4] = {};
    const float* A = g_xpad + (size_t)blockIdx.x * 128 * FTP;
    const float* B = g_W1T + (size_t)blockIdx.y * 64 * FTP;
    mma_mainloop<64, FTP / 32>(A, FTP, B, FTP, acc);
    int lane = threadIdx.x & 31, wid = threadIdx.x >> 5;
    int rb = blockIdx.x * 128 + (wid >> 1) * 32 + (lane >> 2);
    int cb = blockIdx.y * 64 + (wid & 1) * 32 + 2 * (lane & 3);
#pragma unroll
    for (int mt = 0; mt < 2; mt++)
#pragma unroll
        for (int nt = 0; nt < 4; nt++) {
            int r = rb + mt * 16, cc = cb + nt * 8;
            *(float2*)&g_xl[(size_t)r * HD + cc] = make_float2(acc[mt][nt][0], acc[mt][nt][1]);
            *(float2*)&g_xl[(size_t)(r + 8) * HD + cc] = make_float2(acc[mt][nt][2], acc[mt][nt][3]);
        }
}

__global__ void __launch_bounds__(256, 3) k_tgG() {       // G += featc @ BcatT^T (split-K 2)
    float acc[2][2][4] = {};
    int m0 = blockIdx.x * 128, n0 = blockIdx.y * 32, kz = blockIdx.z * 2048;
    const float* A = g_featc + (size_t)m0 * HD + kz;
    const float* B = g_BcatT + (size_t)n0 * HD + kz;
    mma_mainloop<32, 64>(A, HD, B, HD, acc);
    int lane = threadIdx.x & 31, wid = threadIdx.x >> 5;
    int rb = m0 + (wid >> 1) * 32 + (lane >> 2);
    int cb = n0 + (wid & 1) * 16 + 2 * (lane & 3);
#pragma unroll
    for (int mt = 0; mt < 2; mt++)
#pragma unroll
        for (int nt = 0; nt < 2; nt++) {
            int r = rb + mt * 16, cc = cb + nt * 8;
            atomicAdd(&g_G[(size_t)r * GC + cc],           acc[mt][nt][0]);
            atomicAdd(&g_G[(size_t)r * GC + cc + 1],       acc[mt][nt][1]);
            atomicAdd(&g_G[(size_t)(r + 8) * GC + cc],     acc[mt][nt][2]);
            atomicAdd(&g_G[(size_t)(r + 8) * GC + cc + 1], acc[mt][nt][3]);
        }
}

__global__ void __launch_bounds__(256, 3) k_tgMV(const float* __restrict__ Wa) {
    float acc[2][5][4] = {};
    int h = blockIdx.y;
    const float* A = Wa + (size_t)h * HD + (size_t)blockIdx.x * 128 * WAC;
    const float* B = g_Ball + (size_t)h * BR * HD;
    mma_mainloop<80, HD / 32>(A, WAC, B, HD, acc);   // Wa operands tf32-truncated
    int lane = threadIdx.x & 31, wid = threadIdx.x >> 5;
    int k0 = blockIdx.x * 128 + (wid >> 1) * 32 + (lane >> 2);
    int nb = (wid & 1) * 40 + 2 * (lane & 3);
#pragma unroll
    for (int mt = 0; mt < 2; mt++) {
        int k = k0 + mt * 16;
#pragma unroll
        for (int nt = 0; nt < 5; nt++) {
            int n = nb + nt * 8;
            if (n < 64) {
                g_BcatT[(size_t)(h * 64 + n) * HD + k]         = tf32r(acc[mt][nt][0]);
                g_BcatT[(size_t)(h * 64 + n + 1) * HD + k]     = tf32r(acc[mt][nt][1]);
                g_BcatT[(size_t)(h * 64 + n) * HD + k + 8]     = tf32r(acc[mt][nt][2]);
                g_BcatT[(size_t)(h * 64 + n + 1) * HD + k + 8] = tf32r(acc[mt][nt][3]);
            } else if (n == 64) {
                g_V1[k * NH + h]       = acc[mt][nt][0];
                g_V2[k * NH + h]       = acc[mt][nt][1];
                g_V1[(k + 8) * NH + h] = acc[mt][nt][2];
                g_V2[(k + 8) * NH + h] = acc[mt][nt][3];
            }
        }
    }
}

// ---------------- fused prep: xpad | W1T | W2T(+BcatT tail) | zero-G | bw2 ----------------
#define NB_XPAD (NN*FTP/256)          // 2816
#define NB_W1T  ((FTP/32)*(HD/32))    // 5632
#define NB_W2T  ((HD/32)*(NC/32))     // 256
#define NB_GZ   (NN*GC/256)           // 1152
__global__ void __launch_bounds__(256) k_prepA(const float* __restrict__ x,
                                               const float* __restrict__ W1,
                                               const float* __restrict__ W2,
                                               const float* __restrict__ ba) {
    __shared__ float t[32][33];
    __shared__ float red[256];
    int b = blockIdx.x, tid = threadIdx.x;
    if (b < NB_XPAD) {                                   // ---- xpad ----
        int i = b * 256 + tid;
        int r = i / FTP, c = i % FTP;
        g_xpad[i] = (c < FT) ? tf32r(x[r * FT + c]) : 0.0f;
        return;
    }
    b -= NB_XPAD;
    if (b < NB_W1T) {                                    // ---- W1T transpose ----
        int ky = b / (HD / 32), nx = b % (HD / 32);
        int kb = ky * 32, nb = nx * 32;
        int tx = tid & 31, ty = tid >> 5;
        for (int i = ty; i < 32; i += 8) {
            int k = kb + i;
            t[i][tx] = (k < FT) ? tf32r(W1[(size_t)k * HD + nb + tx]) : 0.0f;
        }
        __syncthreads();
        for (int i = ty; i < 32; i += 8)
            g_W1T[(size_t)(nb + i) * FTP + kb + tx] = t[tx][i];
        return;
    }
    b -= NB_W1T;
    if (b < NB_W2T) {                                    // ---- W2T + BcatT tail ----
        int kb = (b >> 1) * 32, nb = (b & 1) * 32;
        int tx = tid & 31, ty = tid >> 5;
        for (int i = ty; i < 32; i += 8)
            t[i][tx] = tf32r(W2[(size_t)(kb + i) * NC + nb + tx]);
        __syncthreads();
        for (int i = ty; i < 32; i += 8) {
            float v = t[tx][i];
            g_W2T[(size_t)(nb + i) * HD + kb + tx] = v;
            g_BcatT[(size_t)(HC + nb + i) * HD + kb + tx] = v;
        }
        return;
    }
    b -= NB_W2T;
    if (b < NB_GZ) {                                     // ---- zero G (split-K atomics) ----
        g_G[b * 256 + tid] = 0.0f;
        return;
    }
    // ---- bw2 = ba @ W2 (1 block) ----
    int c = tid & 63, sl = tid >> 6;
    float acc = 0.0f;
    for (int d = sl * 1024; d < (sl + 1) * 1024; d++) acc += ba[d] * W2[d * NC + c];
    red[tid] = acc;
    __syncthreads();
    if (sl == 0) g_bw2[c] = red[c] + red[c + 64] + red[c + 128] + red[c + 192];
}

__global__ void k_fillB(const float* __restrict__ att) {
    size_t i = (size_t)blockIdx.x * 256 + threadIdx.x;    // NH*BR*HD
    if (i >= (size_t)NH * BR * HD) return;
    int d = (int)(i & (HD - 1));
    int rh = (int)(i >> 12);
    int r = rh % BR, h = rh / BR;
    float v;
    if (r < 64)       v = g_W2T[(size_t)r * HD + d];
    else if (r == 64) v = tf32r(att[h * 2 * HD + d]);
    else if (r == 65) v = tf32r(att[h * 2 * HD + HD + d]);
    else              v = 0.0f;
    g_Ball[i] = v;
}

// ---------------- fused CSR: per-warp count + offset + place (deterministic) ----------------
__global__ void __launch_bounds__(256) k_csr(const int* __restrict__ edge) {
    __shared__ int se_[NNZ];
    int tid = threadIdx.x;
    for (int i = tid; i < NNZ; i += 256) se_[i] = edge[i];
    __syncthreads();
    int lane = tid & 31;
    int e = blockIdx.x * 8 + (tid >> 5);     // one warp per hyperedge
    int nlt = 0, cnt = 0;
    for (int i = lane; i < NNZ; i += 32) {
        int v = se_[i];
        nlt += __popc(__ballot_sync(0xFFFFFFFFu, v < e));
        cnt += __popc(__ballot_sync(0xFFFFFFFFu, v == e));
    }
    int w = nlt;                              // boff[e] = #{values < e}
    for (int i = lane; i < NNZ; i += 32) {
        int v = se_[i];
        unsigned m = __ballot_sync(0xFFFFFFFFu, v == e);
        if (v == e)
            g_csr[w + __popc(m & ((1u << lane) - 1u))] = i;
        w += __popc(m);
    }
    if (lane == 0) {
        g_bcnt[e] = cnt;
        g_boff[e] = nlt;
        g_Binv[e] = (cnt > 0) ? 1.0f / (float)cnt : 0.0f;
    }
}

// ---------------- hgc1 gathers (float4) ----------------
__global__ void __launch_bounds__(256) k_edgefeat() {
    int e = blockIdx.x;
    int d4 = blockIdx.y * 256 + threadIdx.x;
    int off = g_boff[e], cnt = g_bcnt[e];
    float4 acc = make_float4(0.f, 0.f, 0.f, 0.f);
    const float4* xl4 = (const float4*)g_xl;
    for (int t = 0; t < cnt; t++) {
        int i = g_csr[off + t];
        float4 v = xl4[(size_t)(i >> 3) * (HD / 4) + d4];
        acc.x += v.x; acc.y += v.y; acc.z += v.z; acc.w += v.w;
    }
    float bi = g_Binv[e];
    acc.x *= bi; acc.y *= bi; acc.z *= bi; acc.w *= bi;
    ((float4*)g_ef)[(size_t)e * (HD / 4) + d4] = acc;
}
__global__ void __launch_bounds__(256) k_feat(const int* __restrict__ edge,
                                              const float* __restrict__ b1,
                                              float* __restrict__ feat) {
    int n = blockIdx.x;
    int d4 = blockIdx.y * 256 + threadIdx.x;
    float4 acc = make_float4(0.f, 0.f, 0.f, 0.f);
    const float4* ef4 = (const float4*)g_ef;
#pragma unroll
    for (int j = 0; j < KD; j++) {
        int e = edge[n * KD + j];
        float4 v = ef4[(size_t)e * (HD / 4) + d4];
        acc.x += v.x; acc.y += v.y; acc.z += v.z; acc.w += v.w;
    }
    float4 bb = ((const float4*)b1)[d4];
    float4 r, rc;
    r.x = fmaxf(acc.x * DINV + bb.x, 0.f);
    r.y = fmaxf(acc.y * DINV + bb.y, 0.f);
    r.z = fmaxf(acc.z * DINV + bb.z, 0.f);
    r.w = fmaxf(acc.w * DINV + bb.w, 0.f);
    rc.x = tf32r(r.x); rc.y = tf32r(r.y); rc.z = tf32r(r.z); rc.w = tf32r(r.w);
    ((float4*)feat)[(size_t)n * (HD / 4) + d4] = r;       // exact output #1
    ((float4*)g_featc)[(size_t)n * (HD / 4) + d4] = rc;   // rounded A for G gemm
}
__global__ void __launch_bounds__(256) k_he(const float* __restrict__ feat) {
    int e = blockIdx.x;
    int d4 = blockIdx.y * 256 + threadIdx.x;
    int off = g_boff[e], cnt = g_bcnt[e];
    float4 acc = make_float4(0.f, 0.f, 0.f, 0.f);
    const float4* f4 = (const float4*)feat;
    for (int t = 0; t < cnt; t++) {
        int i = g_csr[off + t];
        float4 v = f4[(size_t)(i >> 3) * (HD / 4) + d4];
        acc.x += v.x; acc.y += v.y; acc.z += v.z; acc.w += v.w;
    }
    float inv = 1.0f / (float)cnt;
    acc.x *= inv; acc.y *= inv; acc.z *= inv; acc.w *= inv;
    ((float4*)g_he)[(size_t)e * (HD / 4) + d4] = acc;
}

// ---------------- attention logits + softmax ----------------
__global__ void __launch_bounds__(256) k_sxse(const float* __restrict__ feat) {
    int b = blockIdx.x;
    const float* row; const float* V; float* out;
    if (b < NN) { row = feat + (size_t)b * HD; V = g_V1; out = g_sx + b * NH; }
    else { int e = b - NN; row = g_he + (size_t)e * HD; V = g_V2; out = g_se + e * NH; }
    float acc[NH] = {};
    for (int k = threadIdx.x; k < HD; k += 256) {
        float xv = row[k];
        float4 w0 = *(const float4*)&V[k * NH];
        float4 w1 = *(const float4*)&V[k * NH + 4];
        acc[0] += xv * w0.x; acc[1] += xv * w0.y; acc[2] += xv * w0.z; acc[3] += xv * w0.w;
        acc[4] += xv * w1.x; acc[5] += xv * w1.y; acc[6] += xv * w1.z; acc[7] += xv * w1.w;
    }
    __shared__ float red[NH][256];
#pragma unroll
    for (int h = 0; h < NH; h++) red[h][threadIdx.x] = acc[h];
    __syncthreads();
    for (int s = 128; s > 0; s >>= 1) {
        if (threadIdx.x < s) {
#pragma unroll
            for (int h = 0; h < NH; h++) red[h][threadIdx.x] += red[h][threadIdx.x + s];
        }
        __syncthreads();
    }
    if (threadIdx.x < NH) out[threadIdx.x] = red[threadIdx.x][0];
}
__global__ void k_alpha(const int* __restrict__ edge) {
    int id = blockIdx.x * blockDim.x + threadIdx.x;
    if (id >= NN * NH) return;
    int n = id >> 3, h = id & 7;
    float sxv = g_sx[n * NH + h];
    float l[KD];
    float m = -1e30f;
#pragma unroll
    for (int j = 0; j < KD; j++) {
        int e = edge[n * KD + j];
        float t = sxv + g_se[e * NH + h];
        t = t > 0.0f ? t : 0.2f * t;
        l[j] = t;
        m = fmaxf(m, t);
    }
    float s = 0.0f;
#pragma unroll
    for (int j = 0; j < KD; j++) { l[j] = expf(l[j] - m); s += l[j]; }
    float inv = 1.0f / s;
#pragma unroll
    for (int j = 0; j < KD; j++) g_alpha[(n * KD + j) * NH + h] = l[j] * inv;
}

// ---------------- CODE-space aggregation ----------------
__global__ void __launch_bounds__(256) k_R() {
    int e = blockIdx.x;
    int hc = blockIdx.y * 256 + threadIdx.x;
    int h = hc >> 6;
    int off = g_boff[e], cnt = g_bcnt[e];
    float acc = 0.0f;
    for (int t = 0; t < cnt; t++) {
        int i = g_csr[off + t];
        acc += g_alpha[i * NH + h] * g_G[(i >> 3) * GC + hc];
    }
    g_R[e * HC + hc] = acc * g_Binv[e];
}
__global__ void k_Y(const int* __restrict__ edge) {
    int n = blockIdx.x, c = threadIdx.x;
    float acc = g_G[n * GC + HC + c] + g_bw2[c];
    float s = 0.0f;
#pragma unroll
    for (int j = 0; j < KD; j++) {
        int e = edge[n * KD + j];
        const float* al = &g_alpha[(n * KD + j) * NH];
        const float* Rr = &g_R[e * HC + c];
#pragma unroll
        for (int h = 0; h < NH; h++) s += al[h] * Rr[h * NC];
    }
    g_Y[n * NC + c] = acc + s * DINV * (1.0f / NH);
}
__global__ void k_ef2() {
    int e = blockIdx.x, c = threadIdx.x;
    int off = g_boff[e], cnt = g_bcnt[e];
    float acc = 0.0f;
    for (int t = 0; t < cnt; t++) {
        int i = g_csr[off + t];
        acc += g_Y[(i >> 3) * NC + c];
    }
    g_ef2[e * NC + c] = acc * g_Binv[e];
}
__global__ void k_out(const int* __restrict__ edge, const float* __restrict__ b2,
                      float* __restrict__ out) {
    int n = blockIdx.x, c = threadIdx.x;
    float acc = 0.0f;
#pragma unroll
    for (int j = 0; j < KD; j++) {
        int e = edge[n * KD + j];
        acc += g_ef2[e * NC + c];
    }
    float hid = acc * DINV + b2[c];
    out[(size_t)NN * HD + n * NC + c] = hid;
    out[(size_t)NN * HD + NN * NC + n * NC + c] = tanhf(hid);
}

// ---------------- launch ----------------
extern "C" void kernel_launch(void* const* d_in, const int* in_sizes, int n_in,
                              void* d_out, int out_size) {
    const float* x    = (const float*)d_in[0];
    const int*   edge = (const int*)  d_in[2];
    const float* W1   = (const float*)d_in[3];
    const float* b1   = (const float*)d_in[4];
    const float* Wa   = (const float*)d_in[5];
    const float* att  = (const float*)d_in[6];
    const float* ba   = (const float*)d_in[7];
    const float* W2   = (const float*)d_in[8];
    const float* b2   = (const float*)d_in[9];
    float* out  = (float*)d_out;
    float* feat = out;

    k_csr<<<64, 256>>>(edge);                                         // 1
    k_prepA<<<NB_XPAD + NB_W1T + NB_W2T + NB_GZ + 1, 256>>>(x, W1, W2, ba); // 2
    k_fillB<<<(NH * BR * HD + 255) / 256, 256>>>(att);                // 3
    k_tg1<<<dim3(4, 64), 256>>>();                                    // 4
    k_edgefeat<<<dim3(EE, 4), 256>>>();                               // 5
    k_tgMV<<<dim3(32, 8), 256>>>(Wa);                                 // 6  <- ncu slot
    k_feat<<<dim3(NN, 4), 256>>>(edge, b1, feat);                     // 7
    k_he<<<dim3(EE, 4), 256>>>(feat);                                 // 8
    k_sxse<<<NN + EE, 256>>>(feat);                                   // 9
    k_alpha<<<16, 256>>>(edge);                                       // 10
    k_tgG<<<dim3(4, 18, 2), 256>>>();                                 // 11
    k_R<<<dim3(EE, 2), 256>>>();                                      // 12
    k_Y<<<NN, 64>>>(edge);                                            // 13
    k_ef2<<<EE, 64>>>();                                              // 14
    k_out<<<NN, 64>>>(edge, b2, out);                                 // 15
}